// round 1
// baseline (speedup 1.0000x reference)
#include <cuda_runtime.h>

#define B_    8
#define CIN   256
#define COUT  256
#define H_    64
#define W_    64
#define L_    (H_ * W_)
#define K2_   9

// Scratch (static __device__ arrays — no runtime allocation)
__device__ float  d_wT[CIN * K2_ * COUT];     // weight transposed: [cin][k2][cout]
__device__ int4   d_mi[B_ * K2_ * L_];        // bilinear corner indices (clamped), layout [b][k2][l]
__device__ float4 d_mw[B_ * K2_ * L_];        // bilinear corner weights (validity-masked)

// ---------------------------------------------------------------------------
// Kernel 1: transpose weight [cout][cin][k2] -> [cin][k2][cout]
// ---------------------------------------------------------------------------
__global__ void wt_kernel(const float* __restrict__ w) {
    int i = blockIdx.x * blockDim.x + threadIdx.x;
    if (i >= CIN * K2_ * COUT) return;
    int co = i % COUT;
    int k2 = (i / COUT) % K2_;
    int ci = i / (COUT * K2_);
    d_wT[i] = w[(co * CIN + ci) * K2_ + k2];
}

// ---------------------------------------------------------------------------
// Kernel 2: per-(b, k2, pixel) bilinear sampling metadata from anchors.
// Sample position simplifies to:
//   px = x_ctr + cos*dw*xx - sin*dh*yy
//   py = y_ctr + sin*dw*xx + cos*dh*yy
// (conv-grid terms in offset and deform-conv base cancel exactly)
// ---------------------------------------------------------------------------
__global__ void meta_kernel(const float* __restrict__ anc) {
    int g = blockIdx.x * blockDim.x + threadIdx.x;
    if (g >= B_ * K2_ * L_) return;
    int l  = g % L_;
    int k2 = (g / L_) % K2_;
    int b  = g / (L_ * K2_);

    const float* a = anc + (size_t)(b * L_ + l) * 5;
    float xc = a[0] * 0.125f;            // / stride (8, exact)
    float yc = a[1] * 0.125f;
    float dw = (a[2] * 0.125f) / 3.0f;   // (w/stride)/kernel_size
    float dh = (a[3] * 0.125f) / 3.0f;
    float s, c;
    sincosf(a[4], &s, &c);

    float fx = (float)(k2 % 3) - 1.0f;   // xx[j] = idx[j%3]
    float fy = (float)(k2 / 3) - 1.0f;   // yy[j] = idx[j/3]
    float xk = dw * fx;
    float yk = dh * fy;
    float px = (c * xk - s * yk) + xc;
    float py = (s * xk + c * yk) + yc;

    float x0f = floorf(px), y0f = floorf(py);
    int   x0  = (int)x0f,   y0  = (int)y0f;
    float wx1 = px - x0f,   wy1 = py - y0f;
    float wx0 = 1.0f - wx1, wy0 = 1.0f - wy1;
    int   x1 = x0 + 1, y1 = y0 + 1;

    float vx0 = (x0 >= 0 && x0 < W_) ? 1.0f : 0.0f;
    float vx1 = (x1 >= 0 && x1 < W_) ? 1.0f : 0.0f;
    float vy0 = (y0 >= 0 && y0 < H_) ? 1.0f : 0.0f;
    float vy1 = (y1 >= 0 && y1 < H_) ? 1.0f : 0.0f;

    int xc0 = min(max(x0, 0), W_ - 1), xc1 = min(max(x1, 0), W_ - 1);
    int yc0 = min(max(y0, 0), H_ - 1), yc1 = min(max(y1, 0), H_ - 1);

    d_mi[g] = make_int4(yc0 * W_ + xc0, yc0 * W_ + xc1,
                        yc1 * W_ + xc0, yc1 * W_ + xc1);
    d_mw[g] = make_float4(wy0 * wx0 * vy0 * vx0,
                          wy0 * wx1 * vy0 * vx1,
                          wy1 * wx0 * vy1 * vx0,
                          wy1 * wx1 * vy1 * vx1);
}

// ---------------------------------------------------------------------------
// Kernel 3: implicit GEMM.
//   M tile = 128 pixels, N tile = 128 couts, K chunk = 9 (one cin).
//   256 threads, each computes 8 pixels x 8 couts.
//   ty (pixel group) is the fast thread index -> coalesced float4 stores.
// ---------------------------------------------------------------------------
__global__ __launch_bounds__(256, 2)
void gemm_kernel(const float* __restrict__ x, float* __restrict__ out) {
    __shared__ float  sA[K2_ * 128];       // samples  [k2][pixel]
    __shared__ float  sB[K2_ * 128];       // weights  [k2][cout]
    __shared__ int4   sMi[K2_ * 128];      // bilinear indices for this tile
    __shared__ float4 sMw[K2_ * 128];      // bilinear weights for this tile

    const int tid = threadIdx.x;
    const int mt  = blockIdx.x;            // 0..255
    const int b   = mt >> 5;               // 8 batches * 32 tiles
    const int l0  = (mt & 31) << 7;        // 128 pixels per tile
    const int co0 = blockIdx.y << 7;       // 0 or 128
    const int ty  = tid & 15;              // pixel group (fast)
    const int tx  = tid >> 4;              // cout group

    // Load tile metadata once (reused for all 256 cin)
    for (int s = tid; s < K2_ * 128; s += 256) {
        int k2 = s >> 7, p = s & 127;
        int g = (b * K2_ + k2) * L_ + l0 + p;
        sMi[s] = d_mi[g];
        sMw[s] = d_mw[g];
    }

    float acc[64];
#pragma unroll
    for (int i = 0; i < 64; ++i) acc[i] = 0.0f;

    const float* xb = x + (size_t)b * CIN * L_;

    for (int ci = 0; ci < CIN; ++ci) {
        __syncthreads();   // also covers metadata prologue on first iteration
        const float* plane = xb + ci * L_;
        const float* wrow  = d_wT + ci * (K2_ * COUT) + co0;

        for (int s = tid; s < K2_ * 128; s += 256) {
            int k2 = s >> 7, p = s & 127;
            sB[s] = wrow[(k2 << 8) + p];
            int4   ii = sMi[s];
            float4 ww = sMw[s];
            float v = ww.x * __ldg(plane + ii.x)
                    + ww.y * __ldg(plane + ii.y)
                    + ww.z * __ldg(plane + ii.z)
                    + ww.w * __ldg(plane + ii.w);
            sA[s] = v;
        }
        __syncthreads();

#pragma unroll
        for (int kk = 0; kk < K2_; ++kk) {
            float4 a0 = *(const float4*)&sA[(kk << 7) + (ty << 3)];
            float4 a1 = *(const float4*)&sA[(kk << 7) + (ty << 3) + 4];
            float4 b0 = *(const float4*)&sB[(kk << 7) + (tx << 3)];
            float4 b1 = *(const float4*)&sB[(kk << 7) + (tx << 3) + 4];
            float av[8] = {a0.x, a0.y, a0.z, a0.w, a1.x, a1.y, a1.z, a1.w};
            float bv[8] = {b0.x, b0.y, b0.z, b0.w, b1.x, b1.y, b1.z, b1.w};
#pragma unroll
            for (int i = 0; i < 8; ++i)
#pragma unroll
                for (int j = 0; j < 8; ++j)
                    acc[i * 8 + j] = fmaf(av[i], bv[j], acc[i * 8 + j]);
        }
    }

    // Epilogue: relu + coalesced float4 stores (pixel index fastest)
#pragma unroll
    for (int j = 0; j < 8; ++j) {
        int co = co0 + (tx << 3) + j;
        float* op = out + ((size_t)(b * COUT + co)) * L_ + l0 + (ty << 3);
        float4 v0, v1;
        v0.x = fmaxf(acc[0 * 8 + j], 0.0f);
        v0.y = fmaxf(acc[1 * 8 + j], 0.0f);
        v0.z = fmaxf(acc[2 * 8 + j], 0.0f);
        v0.w = fmaxf(acc[3 * 8 + j], 0.0f);
        v1.x = fmaxf(acc[4 * 8 + j], 0.0f);
        v1.y = fmaxf(acc[5 * 8 + j], 0.0f);
        v1.z = fmaxf(acc[6 * 8 + j], 0.0f);
        v1.w = fmaxf(acc[7 * 8 + j], 0.0f);
        *(float4*)op       = v0;
        *(float4*)(op + 4) = v1;
    }
}

// ---------------------------------------------------------------------------
extern "C" void kernel_launch(void* const* d_in, const int* in_sizes, int n_in,
                              void* d_out, int out_size) {
    const float* x   = (const float*)d_in[0];  // [8,256,64,64]
    const float* anc = (const float*)d_in[1];  // [8,4096,5]
    const float* w   = (const float*)d_in[2];  // [256,256,3,3]
    float* out = (float*)d_out;                // [8,256,64,64]

    wt_kernel<<<(CIN * K2_ * COUT + 255) / 256, 256>>>(w);
    meta_kernel<<<(B_ * K2_ * L_ + 255) / 256, 256>>>(anc);
    gemm_kernel<<<dim3(256, 2), 256>>>(x, out);
}

// round 2
// speedup vs baseline: 1.3076x; 1.3076x over previous
#include <cuda_runtime.h>

#define B_    8
#define CIN   256
#define COUT  256
#define H_    64
#define W_    64
#define L_    (H_ * W_)
#define K2_   9

// Scratch (static __device__ arrays — no runtime allocation)
__device__ float  d_wT[CIN * K2_ * COUT];     // weight transposed: [cin][k2][cout]
__device__ int4   d_mi[B_ * K2_ * L_];        // bilinear corner indices, [b][k2][l]
__device__ float4 d_mw[B_ * K2_ * L_];        // bilinear corner weights (masked)

// ---------------------------------------------------------------------------
// packed f32x2 helpers (Blackwell FFMA2 path)
// ---------------------------------------------------------------------------
__device__ __forceinline__ unsigned long long pack2(float lo, float hi) {
    unsigned long long r;
    asm("mov.b64 %0, {%1, %2};" : "=l"(r) : "f"(lo), "f"(hi));
    return r;
}
__device__ __forceinline__ void fma2(unsigned long long& d,
                                     unsigned long long a,
                                     unsigned long long b) {
    asm("fma.rn.f32x2 %0, %1, %2, %0;" : "+l"(d) : "l"(a), "l"(b));
}
__device__ __forceinline__ float2 unpack2(unsigned long long v) {
    float lo, hi;
    asm("mov.b64 {%0, %1}, %2;" : "=f"(lo), "=f"(hi) : "l"(v));
    return make_float2(lo, hi);
}

// ---------------------------------------------------------------------------
// Kernel 1: transpose weight [cout][cin][k2] -> [cin][k2][cout]
// ---------------------------------------------------------------------------
__global__ void wt_kernel(const float* __restrict__ w) {
    int i = blockIdx.x * blockDim.x + threadIdx.x;
    if (i >= CIN * K2_ * COUT) return;
    int co = i % COUT;
    int k2 = (i / COUT) % K2_;
    int ci = i / (COUT * K2_);
    d_wT[i] = w[(co * CIN + ci) * K2_ + k2];
}

// ---------------------------------------------------------------------------
// Kernel 2: bilinear sampling metadata. Sample position simplifies to
//   px = x_ctr + cos*dw*xx - sin*dh*yy ; py = y_ctr + sin*dw*xx + cos*dh*yy
// ---------------------------------------------------------------------------
__global__ void meta_kernel(const float* __restrict__ anc) {
    int g = blockIdx.x * blockDim.x + threadIdx.x;
    if (g >= B_ * K2_ * L_) return;
    int l  = g % L_;
    int k2 = (g / L_) % K2_;
    int b  = g / (L_ * K2_);

    const float* a = anc + (size_t)(b * L_ + l) * 5;
    float xc = a[0] * 0.125f;
    float yc = a[1] * 0.125f;
    float dw = (a[2] * 0.125f) / 3.0f;
    float dh = (a[3] * 0.125f) / 3.0f;
    float s, c;
    sincosf(a[4], &s, &c);

    float fx = (float)(k2 % 3) - 1.0f;
    float fy = (float)(k2 / 3) - 1.0f;
    float xk = dw * fx;
    float yk = dh * fy;
    float px = (c * xk - s * yk) + xc;
    float py = (s * xk + c * yk) + yc;

    float x0f = floorf(px), y0f = floorf(py);
    int   x0  = (int)x0f,   y0  = (int)y0f;
    float wx1 = px - x0f,   wy1 = py - y0f;
    float wx0 = 1.0f - wx1, wy0 = 1.0f - wy1;
    int   x1 = x0 + 1, y1 = y0 + 1;

    float vx0 = (x0 >= 0 && x0 < W_) ? 1.0f : 0.0f;
    float vx1 = (x1 >= 0 && x1 < W_) ? 1.0f : 0.0f;
    float vy0 = (y0 >= 0 && y0 < H_) ? 1.0f : 0.0f;
    float vy1 = (y1 >= 0 && y1 < H_) ? 1.0f : 0.0f;

    int xc0 = min(max(x0, 0), W_ - 1), xc1 = min(max(x1, 0), W_ - 1);
    int yc0 = min(max(y0, 0), H_ - 1), yc1 = min(max(y1, 0), H_ - 1);

    d_mi[g] = make_int4(yc0 * W_ + xc0, yc0 * W_ + xc1,
                        yc1 * W_ + xc0, yc1 * W_ + xc1);
    d_mw[g] = make_float4(wy0 * wx0 * vy0 * vx0,
                          wy0 * wx1 * vy0 * vx1,
                          wy1 * wx0 * vy1 * vx0,
                          wy1 * wx1 * vy1 * vx1);
}

// ---------------------------------------------------------------------------
// Kernel 3: implicit GEMM with packed f32x2 math.
//   Block tile: 256 pixels x 128 couts. 256 threads, each 16 px x 8 couts
//   held as 64 f32x2 accumulators (pixel pairs in the two lanes).
//   sA is XOR-swizzled so the stride-64B A-fragment LDS.128 reads are
//   bank-conflict-free; B-fragment reads are warp-broadcast.
// ---------------------------------------------------------------------------
__global__ __launch_bounds__(256, 1)
void gemm_kernel(const float* __restrict__ x, float* __restrict__ out) {
    __shared__ float sA[K2_ * 256];   // samples [k2][256 px], swizzled
    __shared__ float sB[K2_ * 128];   // weights [k2][128 couts]

    const int tid = threadIdx.x;
    const int bt  = blockIdx.x;            // 0..127
    const int b   = bt >> 4;                // 16 tiles per batch
    const int l0  = (bt & 15) << 8;         // 256 pixels per tile
    const int co0 = blockIdx.y << 7;        // 0 or 128
    const int ty  = tid & 15;               // pixel group (16 px each)
    const int tx  = tid >> 4;               // cout group (8 couts each)

    unsigned long long acc[64];
#pragma unroll
    for (int i = 0; i < 64; ++i) acc[i] = 0ull;

    const float*  xb = x + (size_t)b * CIN * L_;
    const int4*   mi = d_mi + (size_t)b * K2_ * L_ + l0 + tid;  // this thread's pixel
    const float4* mw = d_mw + (size_t)b * K2_ * L_ + l0 + tid;

    // swizzled store slot for this thread's pixel (p = tid)
    const int p_sw  = tid ^ (((tid >> 5) & 3) << 2);
    const int a_sw  = ((ty >> 1) & 3) << 2;   // read-side XOR for A fragments

    for (int ci = 0; ci < CIN; ++ci) {
        const float* plane = xb + ci * L_;
        const float* wrow  = d_wT + ci * (K2_ * COUT) + co0;

        __syncthreads();   // previous compute done before overwriting tiles

        // gather: this thread produces pixel p=tid for all 9 kernel taps
#pragma unroll
        for (int k2 = 0; k2 < K2_; ++k2) {
            int4   ii = mi[k2 * L_];
            float4 ww = mw[k2 * L_];
            float v = ww.x * __ldg(plane + ii.x)
                    + ww.y * __ldg(plane + ii.y)
                    + ww.z * __ldg(plane + ii.z)
                    + ww.w * __ldg(plane + ii.w);
            sA[(k2 << 8) + p_sw] = v;
        }
        // weights tile: 1152 floats
#pragma unroll
        for (int r = 0; r < 5; ++r) {
            int s = tid + (r << 8);
            if (s < K2_ * 128) {
                int kk = s >> 7, j = s & 127;
                sB[s] = wrow[(kk << 8) + j];
            }
        }
        __syncthreads();

#pragma unroll
        for (int kk = 0; kk < K2_; ++kk) {
            const float* aRow = sA + (kk << 8) + (ty << 4);
            // 16 pixels as 8 packed pairs (swizzle-corrected 16B loads)
            ulonglong2 a01 = *(const ulonglong2*)(aRow + (0  ^ a_sw));
            ulonglong2 a23 = *(const ulonglong2*)(aRow + (4  ^ a_sw));
            ulonglong2 a45 = *(const ulonglong2*)(aRow + (8  ^ a_sw));
            ulonglong2 a67 = *(const ulonglong2*)(aRow + (12 ^ a_sw));
            unsigned long long a2[8] = {a01.x, a01.y, a23.x, a23.y,
                                        a45.x, a45.y, a67.x, a67.y};
            float4 b03 = *(const float4*)(sB + (kk << 7) + (tx << 3));
            float4 b47 = *(const float4*)(sB + (kk << 7) + (tx << 3) + 4);
            unsigned long long b2[8] = {
                pack2(b03.x, b03.x), pack2(b03.y, b03.y),
                pack2(b03.z, b03.z), pack2(b03.w, b03.w),
                pack2(b47.x, b47.x), pack2(b47.y, b47.y),
                pack2(b47.z, b47.z), pack2(b47.w, b47.w)};
#pragma unroll
            for (int pi = 0; pi < 8; ++pi)
#pragma unroll
                for (int j = 0; j < 8; ++j)
                    fma2(acc[pi * 8 + j], a2[pi], b2[j]);
        }
    }

    // Epilogue: relu + float4 stores (16 consecutive pixels per thread)
#pragma unroll
    for (int j = 0; j < 8; ++j) {
        float* op = out + ((size_t)(b * COUT + co0 + (tx << 3) + j)) * L_
                        + l0 + (ty << 4);
#pragma unroll
        for (int q = 0; q < 4; ++q) {
            float2 p0 = unpack2(acc[(q * 2) * 8 + j]);
            float2 p1 = unpack2(acc[(q * 2 + 1) * 8 + j]);
            float4 v;
            v.x = fmaxf(p0.x, 0.0f);
            v.y = fmaxf(p0.y, 0.0f);
            v.z = fmaxf(p1.x, 0.0f);
            v.w = fmaxf(p1.y, 0.0f);
            *(float4*)(op + (q << 2)) = v;
        }
    }
}

// ---------------------------------------------------------------------------
extern "C" void kernel_launch(void* const* d_in, const int* in_sizes, int n_in,
                              void* d_out, int out_size) {
    const float* x   = (const float*)d_in[0];  // [8,256,64,64]
    const float* anc = (const float*)d_in[1];  // [8,4096,5]
    const float* w   = (const float*)d_in[2];  // [256,256,3,3]
    float* out = (float*)d_out;                // [8,256,64,64]

    wt_kernel<<<(CIN * K2_ * COUT + 255) / 256, 256>>>(w);
    meta_kernel<<<(B_ * K2_ * L_ + 255) / 256, 256>>>(anc);
    gemm_kernel<<<dim3(128, 2), 256>>>(x, out);
}

// round 4
// speedup vs baseline: 2.9907x; 2.2872x over previous
#include <cuda_runtime.h>
#include <cuda_bf16.h>

#define B_    8
#define CIN   256
#define COUT  256
#define H_    64
#define W_    64
#define L_    4096
#define K2_   9
#define NCH   144        // 9 k2 * 16 ci-chunks of 16

// Scratch (static __device__ arrays — no runtime allocation)
__device__ int4     d_mi[B_ * K2_ * L_];     // bilinear corner indices [b][k2][l]
__device__ float4   d_mw[B_ * K2_ * L_];     // bilinear corner weights (masked)
__device__ unsigned d_Bf[NCH * 4096];        // B fragments, [chunk][hi|lo][tile][lane][reg]

// ---------------------------------------------------------------------------
__device__ __forceinline__ unsigned packbf(float hi, float lo) {
    unsigned r;
    asm("cvt.rn.bf16x2.f32 %0, %1, %2;" : "=r"(r) : "f"(hi), "f"(lo));
    return r;
}
__device__ __forceinline__ void mma_bf16(float* d, const unsigned* a,
                                         const unsigned* b) {
    asm volatile(
        "mma.sync.aligned.m16n8k16.row.col.f32.bf16.bf16.f32 "
        "{%0,%1,%2,%3}, {%4,%5,%6,%7}, {%8,%9}, {%0,%1,%2,%3};"
        : "+f"(d[0]), "+f"(d[1]), "+f"(d[2]), "+f"(d[3])
        : "r"(a[0]), "r"(a[1]), "r"(a[2]), "r"(a[3]), "r"(b[0]), "r"(b[1]));
}

// ---------------------------------------------------------------------------
// Kernel 1: bilinear metadata (validated, rel_err 1.4e-6 in fp32 path)
// ---------------------------------------------------------------------------
__global__ void meta_kernel(const float* __restrict__ anc) {
    int g = blockIdx.x * blockDim.x + threadIdx.x;
    if (g >= B_ * K2_ * L_) return;
    int l = g % L_, k2 = (g / L_) % K2_, b = g / (L_ * K2_);

    const float* a = anc + (size_t)(b * L_ + l) * 5;
    float xc = a[0] * 0.125f, yc = a[1] * 0.125f;
    float dw = (a[2] * 0.125f) / 3.0f, dh = (a[3] * 0.125f) / 3.0f;
    float s, c;
    sincosf(a[4], &s, &c);
    float fx = (float)(k2 % 3) - 1.0f, fy = (float)(k2 / 3) - 1.0f;
    float xk = dw * fx, yk = dh * fy;
    float px = (c * xk - s * yk) + xc;
    float py = (s * xk + c * yk) + yc;

    float x0f = floorf(px), y0f = floorf(py);
    int x0 = (int)x0f, y0 = (int)y0f;
    float wx1 = px - x0f, wy1 = py - y0f;
    float wx0 = 1.0f - wx1, wy0 = 1.0f - wy1;
    int x1 = x0 + 1, y1 = y0 + 1;
    float vx0 = (x0 >= 0 && x0 < W_) ? 1.f : 0.f;
    float vx1 = (x1 >= 0 && x1 < W_) ? 1.f : 0.f;
    float vy0 = (y0 >= 0 && y0 < H_) ? 1.f : 0.f;
    float vy1 = (y1 >= 0 && y1 < H_) ? 1.f : 0.f;
    int xc0 = min(max(x0, 0), W_ - 1), xc1 = min(max(x1, 0), W_ - 1);
    int yc0 = min(max(y0, 0), H_ - 1), yc1 = min(max(y1, 0), H_ - 1);
    d_mi[g] = make_int4(yc0 * W_ + xc0, yc0 * W_ + xc1,
                        yc1 * W_ + xc0, yc1 * W_ + xc1);
    d_mw[g] = make_float4(wy0 * wx0 * vy0 * vx0, wy0 * wx1 * vy0 * vx1,
                          wy1 * wx0 * vy1 * vx0, wy1 * wx1 * vy1 * vx1);
}

// ---------------------------------------------------------------------------
// Kernel 2: bake B into mma fragment order, bf16 hi/lo split.
// Word = d_Bf[chunk*4096 + mat*2048 + tile*64 + lane*2 + reg]
//   co = tile*8 + lane/4 ; k = 2*(lane&3) + 8*reg ; ci = (chunk&15)*16 + k
// ---------------------------------------------------------------------------
__global__ void bf_kernel(const float* __restrict__ w) {
    int i = blockIdx.x * blockDim.x + threadIdx.x;
    if (i >= NCH * 4096) return;
    int chunk = i >> 12;
    int rem   = i & 4095;
    int mat   = rem >> 11;
    int r2    = rem & 2047;
    int tile  = r2 >> 6;
    int lane  = (r2 >> 1) & 31;
    int reg   = r2 & 1;

    int co = tile * 8 + (lane >> 2);
    int kb = 2 * (lane & 3) + 8 * reg;
    int ci = (chunk & 15) * 16 + kb;
    int k2 = chunk >> 4;

    float v0 = w[((size_t)co * CIN + ci) * K2_ + k2];
    float v1 = w[((size_t)co * CIN + ci + 1) * K2_ + k2];

    unsigned hw = packbf(v1, v0);
    float h0 = __uint_as_float(hw << 16);
    float h1 = __uint_as_float(hw & 0xFFFF0000u);
    unsigned lw = packbf(v1 - h1, v0 - h0);
    d_Bf[i] = mat ? lw : hw;
}

// ---------------------------------------------------------------------------
// Kernel 3: implicit GEMM via mma.sync bf16 (3-term split).
//   CTA: M=128 px, N=256 couts, 256 threads = 8 warps (2M x 4N, warp 64x64).
//   K: 144 chunks of 16 (fixed k2). Double-buffered fragment-order smem.
//   Smem per buf: Ah 4K | Al 4K | Bh 8K | Bl 8K = 24KB; two bufs = 48KB.
// ---------------------------------------------------------------------------
__global__ __launch_bounds__(256)
void gemm_kernel(const float* __restrict__ x, float* __restrict__ out) {
    __shared__ uint4 smem4[3072];          // 48 KB
    char* smem = (char*)smem4;

    const int tid  = threadIdx.x;
    const int lane = tid & 31;
    const int wid  = tid >> 5;
    const int mrow = wid & 1;              // M half (64 px)
    const int ncol = wid >> 1;             // N quarter (64 couts)
    const int b    = blockIdx.x >> 5;
    const int l0   = (blockIdx.x & 31) << 7;
    const int px   = tid & 127;
    const int half = tid >> 7;             // k-octant (c 0-7 / 8-15)

    // --- producer A STS byte offsets (4 k-pairs), swizzled fragment order ---
    int sa[4];
#pragma unroll
    for (int t = 0; t < 4; ++t) {
        int ch16 = ((px >> 4) << 5) + ((px & 7) << 2) + t;
        int swz  = ch16 ^ ((ch16 >> 3) & 7);
        sa[t] = ((swz << 2) + ((px >> 3) & 1) + (half << 1)) << 2;
    }
    // --- consumer A fragment offsets (4 m16 tiles) ---
    int ca[4];
#pragma unroll
    for (int i = 0; i < 4; ++i) {
        int ch16 = (mrow * 4 + i) * 32 + lane;
        ca[i] = (ch16 ^ ((ch16 >> 3) & 7)) << 4;
    }
    // --- consumer B fragment offsets (8 n8 tiles) ---
    int bo[8];
#pragma unroll
    for (int t = 0; t < 8; ++t)
        bo[t] = (((ncol * 8 + t) * 64) + lane * 2) << 2;

    float acc[4][8][4];
#pragma unroll
    for (int i = 0; i < 4; ++i)
#pragma unroll
        for (int t = 0; t < 8; ++t)
#pragma unroll
            for (int r = 0; r < 4; ++r) acc[i][t][r] = 0.0f;

    const float* xb = x + (size_t)b * CIN * L_;
    int4 mi4; float4 mw4;
    {   // metadata for k2 = 0
        int mx = (b * K2_ + 0) * L_ + l0 + px;
        mi4 = d_mi[mx]; mw4 = d_mw[mx];
    }

    // ---- prologue: fill buffer 0 with chunk 0 ----
    {
        const float* plane = xb + (size_t)(half * 8) * L_;
        float v[8];
#pragma unroll
        for (int e = 0; e < 8; ++e) {
            const float* pl = plane + e * L_;
            v[e] = mw4.x * __ldg(pl + mi4.x) + mw4.y * __ldg(pl + mi4.y)
                 + mw4.z * __ldg(pl + mi4.z) + mw4.w * __ldg(pl + mi4.w);
        }
        char* A = smem;
#pragma unroll
        for (int t = 0; t < 4; ++t) {
            unsigned hw = packbf(v[2 * t + 1], v[2 * t]);
            float h0 = __uint_as_float(hw << 16);
            float h1 = __uint_as_float(hw & 0xFFFF0000u);
            unsigned lw = packbf(v[2 * t + 1] - h1, v[2 * t] - h0);
            *(unsigned*)(A + sa[t])        = hw;
            *(unsigned*)(A + 4096 + sa[t]) = lw;
        }
        const uint4* src = (const uint4*)d_Bf;
        uint4* dst = (uint4*)(smem + 8192);
#pragma unroll
        for (int i = 0; i < 4; ++i)
            dst[tid + i * 256] = __ldg(src + tid + i * 256);
    }
    __syncthreads();

    for (int ch = 0; ch < NCH; ++ch) {
        const int buf = ch & 1;
        const bool more = (ch + 1) < NCH;
        float v[8];
        uint4 bre[4];
        if (more) {
            const int nc = ch + 1;
            if ((nc & 15) == 0) {
                int mx = (b * K2_ + (nc >> 4)) * L_ + l0 + px;
                mi4 = d_mi[mx]; mw4 = d_mw[mx];
            }
            const float* plane = xb + (size_t)((nc & 15) * 16 + half * 8) * L_;
#pragma unroll
            for (int e = 0; e < 8; ++e) {
                const float* pl = plane + e * L_;
                v[e] = mw4.x * __ldg(pl + mi4.x) + mw4.y * __ldg(pl + mi4.y)
                     + mw4.z * __ldg(pl + mi4.z) + mw4.w * __ldg(pl + mi4.w);
            }
            const uint4* src = (const uint4*)(d_Bf + nc * 4096);
#pragma unroll
            for (int i = 0; i < 4; ++i)
                bre[i] = __ldg(src + tid + i * 256);
        }

        // ---- math on current buffer: 3 passes x 32 mma ----
        char* Ab = smem + buf * 24576;
#pragma unroll
        for (int pass = 0; pass < 3; ++pass) {
            const char* Ap = Ab + ((pass == 1) ? 4096 : 0);
            const char* Bp = Ab + 8192 + ((pass == 2) ? 8192 : 0);
            uint4 af[4];
            uint2 bf[8];
#pragma unroll
            for (int i = 0; i < 4; ++i) af[i] = *(const uint4*)(Ap + ca[i]);
#pragma unroll
            for (int t = 0; t < 8; ++t) bf[t] = *(const uint2*)(Bp + bo[t]);
#pragma unroll
            for (int i = 0; i < 4; ++i)
#pragma unroll
                for (int t = 0; t < 8; ++t)
                    mma_bf16(acc[i][t], (const unsigned*)&af[i],
                             (const unsigned*)&bf[t]);
        }

        if (more) {
            char* An = smem + (buf ^ 1) * 24576;
#pragma unroll
            for (int t = 0; t < 4; ++t) {
                unsigned hw = packbf(v[2 * t + 1], v[2 * t]);
                float h0 = __uint_as_float(hw << 16);
                float h1 = __uint_as_float(hw & 0xFFFF0000u);
                unsigned lw = packbf(v[2 * t + 1] - h1, v[2 * t] - h0);
                *(unsigned*)(An + sa[t])        = hw;
                *(unsigned*)(An + 4096 + sa[t]) = lw;
            }
            uint4* dst = (uint4*)(An + 8192);
#pragma unroll
            for (int i = 0; i < 4; ++i)
                dst[tid + i * 256] = bre[i];
        }
        __syncthreads();
    }

    // ---- epilogue: relu + direct stores (4 full 32B sectors per STG) ----
#pragma unroll
    for (int i = 0; i < 4; ++i) {
        int pxg = l0 + (mrow * 4 + i) * 16 + (lane >> 2);
#pragma unroll
        for (int t = 0; t < 8; ++t) {
            int co = ncol * 64 + t * 8 + 2 * (lane & 3);
            float* o0 = out + ((size_t)(b * COUT + co)) * L_ + pxg;
            float* o1 = o0 + L_;
            o0[0] = fmaxf(acc[i][t][0], 0.0f);
            o1[0] = fmaxf(acc[i][t][1], 0.0f);
            o0[8] = fmaxf(acc[i][t][2], 0.0f);
            o1[8] = fmaxf(acc[i][t][3], 0.0f);
        }
    }
}

// ---------------------------------------------------------------------------
extern "C" void kernel_launch(void* const* d_in, const int* in_sizes, int n_in,
                              void* d_out, int out_size) {
    const float* x   = (const float*)d_in[0];  // [8,256,64,64]
    const float* anc = (const float*)d_in[1];  // [8,4096,5]
    const float* w   = (const float*)d_in[2];  // [256,256,3,3]
    float* out = (float*)d_out;                // [8,256,64,64]

    meta_kernel<<<(B_ * K2_ * L_ + 255) / 256, 256>>>(anc);
    bf_kernel<<<(NCH * 4096 + 255) / 256, 256>>>(w);
    gemm_kernel<<<256, 256>>>(x, out);
}

// round 5
// speedup vs baseline: 3.4638x; 1.1582x over previous
#include <cuda_runtime.h>
#include <cuda_bf16.h>

#define B_    8
#define CIN   256
#define COUT  256
#define H_    64
#define W_    64
#define L_    4096
#define K2_   9
#define NCH   144        // 9 k2 * 16 ci-chunks of 16

// per-buffer smem: Ah 2K | Al 2K | Bh 8K | Bl 8K
#define BUF_BYTES 20480

// Scratch (static __device__ arrays — no runtime allocation)
__device__ int4     d_mi[B_ * K2_ * L_];     // bilinear corner indices [b][k2][l]
__device__ float4   d_mw[B_ * K2_ * L_];     // bilinear corner weights (masked)
__device__ unsigned d_Bf[NCH * 4096];        // B frags [chunk][mat][tile][lane][reg]

// ---------------------------------------------------------------------------
__device__ __forceinline__ unsigned packbf(float hi, float lo) {
    unsigned r;
    asm("cvt.rn.bf16x2.f32 %0, %1, %2;" : "=r"(r) : "f"(hi), "f"(lo));
    return r;
}
__device__ __forceinline__ void mma_bf16(float* d, const unsigned* a,
                                         const unsigned* b) {
    asm volatile(
        "mma.sync.aligned.m16n8k16.row.col.f32.bf16.bf16.f32 "
        "{%0,%1,%2,%3}, {%4,%5,%6,%7}, {%8,%9}, {%0,%1,%2,%3};"
        : "+f"(d[0]), "+f"(d[1]), "+f"(d[2]), "+f"(d[3])
        : "r"(a[0]), "r"(a[1]), "r"(a[2]), "r"(a[3]), "r"(b[0]), "r"(b[1]));
}
__device__ __forceinline__ void cp16(unsigned dst, const void* src) {
    asm volatile("cp.async.cg.shared.global [%0], [%1], 16;"
                 :: "r"(dst), "l"(src));
}
#define CP_COMMIT() asm volatile("cp.async.commit_group;" ::: "memory")
#define CP_WAIT0()  asm volatile("cp.async.wait_group 0;" ::: "memory")

// ---------------------------------------------------------------------------
// Kernel 1: bilinear metadata (validated)
// ---------------------------------------------------------------------------
__global__ void meta_kernel(const float* __restrict__ anc) {
    int g = blockIdx.x * blockDim.x + threadIdx.x;
    if (g >= B_ * K2_ * L_) return;
    int l = g % L_, k2 = (g / L_) % K2_, b = g / (L_ * K2_);

    const float* a = anc + (size_t)(b * L_ + l) * 5;
    float xc = a[0] * 0.125f, yc = a[1] * 0.125f;
    float dw = (a[2] * 0.125f) / 3.0f, dh = (a[3] * 0.125f) / 3.0f;
    float s, c;
    sincosf(a[4], &s, &c);
    float fx = (float)(k2 % 3) - 1.0f, fy = (float)(k2 / 3) - 1.0f;
    float xk = dw * fx, yk = dh * fy;
    float px = (c * xk - s * yk) + xc;
    float py = (s * xk + c * yk) + yc;

    float x0f = floorf(px), y0f = floorf(py);
    int x0 = (int)x0f, y0 = (int)y0f;
    float wx1 = px - x0f, wy1 = py - y0f;
    float wx0 = 1.0f - wx1, wy0 = 1.0f - wy1;
    int x1 = x0 + 1, y1 = y0 + 1;
    float vx0 = (x0 >= 0 && x0 < W_) ? 1.f : 0.f;
    float vx1 = (x1 >= 0 && x1 < W_) ? 1.f : 0.f;
    float vy0 = (y0 >= 0 && y0 < H_) ? 1.f : 0.f;
    float vy1 = (y1 >= 0 && y1 < H_) ? 1.f : 0.f;
    int xc0 = min(max(x0, 0), W_ - 1), xc1 = min(max(x1, 0), W_ - 1);
    int yc0 = min(max(y0, 0), H_ - 1), yc1 = min(max(y1, 0), H_ - 1);
    d_mi[g] = make_int4(yc0 * W_ + xc0, yc0 * W_ + xc1,
                        yc1 * W_ + xc0, yc1 * W_ + xc1);
    d_mw[g] = make_float4(wy0 * wx0 * vy0 * vx0, wy0 * wx1 * vy0 * vx1,
                          wy1 * wx0 * vy1 * vx0, wy1 * wx1 * vy1 * vx1);
}

// ---------------------------------------------------------------------------
// Kernel 2: bake B into mma fragment order, bf16 hi/lo split (validated R4).
// ---------------------------------------------------------------------------
__global__ void bf_kernel(const float* __restrict__ w) {
    int i = blockIdx.x * blockDim.x + threadIdx.x;
    if (i >= NCH * 4096) return;
    int chunk = i >> 12;
    int rem   = i & 4095;
    int mat   = rem >> 11;
    int r2    = rem & 2047;
    int tile  = r2 >> 6;
    int lane  = (r2 >> 1) & 31;
    int reg   = r2 & 1;

    int co = tile * 8 + (lane >> 2);
    int kb = 2 * (lane & 3) + 8 * reg;
    int ci = (chunk & 15) * 16 + kb;
    int k2 = chunk >> 4;

    float v0 = w[((size_t)co * CIN + ci) * K2_ + k2];
    float v1 = w[((size_t)co * CIN + ci + 1) * K2_ + k2];

    unsigned hw = packbf(v1, v0);
    float h0 = __uint_as_float(hw << 16);
    float h1 = __uint_as_float(hw & 0xFFFF0000u);
    unsigned lw = packbf(v1 - h1, v0 - h0);
    d_Bf[i] = mat ? lw : hw;
}

// ---------------------------------------------------------------------------
// Kernel 3: implicit GEMM, mma.sync bf16 3-term split.
//   CTA: M=64 px x N=256 couts, 256 threads (8 warps: 2M x 4N, warp 32x64).
//   acc = 64 regs/thread. B staged with cp.async. Double-buffered smem.
// ---------------------------------------------------------------------------
__global__ __launch_bounds__(256)
void gemm_kernel(const float* __restrict__ x, float* __restrict__ out) {
    __shared__ uint4 smem4[2 * BUF_BYTES / 16];
    char* smem = (char*)smem4;
    const unsigned smem_b = (unsigned)__cvta_generic_to_shared(smem);

    const int tid  = threadIdx.x;
    const int lane = tid & 31;
    const int wid  = tid >> 5;
    const int b    = blockIdx.x >> 6;
    const int l0   = (blockIdx.x & 63) << 6;   // 64-pixel tiles
    const int px   = tid & 63;
    const int j    = tid >> 6;                 // ci quartet (4 ci each)

    // --- producer A STS byte offsets (2 k-pairs: p = 2j, 2j+1) ---
    const int r  = px & 15, mt = px >> 4;
    const int rs = (r >> 1) & 3;
    int sa[2];
#pragma unroll
    for (int t = 0; t < 2; ++t) {
        int p = 2 * j + t;
        int g = mt * 32 + ((((r & 7) << 2) | (p & 3)) ^ rs);
        sa[t] = g * 16 + (2 * (p >= 4) + (r >= 8)) * 4;
    }
    // --- consumer A fragment offsets (2 m16 tiles per warp) ---
    int ca[2];
#pragma unroll
    for (int i = 0; i < 2; ++i) {
        int mtc = (wid & 1) * 2 + i;
        ca[i] = (mtc * 32 + (lane ^ ((lane >> 3) & 3))) * 16;
    }
    // --- consumer B fragment offsets (8 n8 tiles per warp) ---
    const int ncol = wid >> 1;
    int bo[8];
#pragma unroll
    for (int t = 0; t < 8; ++t)
        bo[t] = (((ncol * 8 + t) * 64) + lane * 2) << 2;

    float acc[2][8][4];
#pragma unroll
    for (int i = 0; i < 2; ++i)
#pragma unroll
        for (int t = 0; t < 8; ++t)
#pragma unroll
            for (int q = 0; q < 4; ++q) acc[i][t][q] = 0.0f;

    const float* xb = x + (size_t)b * CIN * L_;
    int4 mi4; float4 mw4;
    {
        int mx = (b * K2_) * L_ + l0 + px;
        mi4 = d_mi[mx]; mw4 = d_mw[mx];
    }

    // ---- prologue: fill buffer 0 with chunk 0 ----
    {
        const float* plane = xb + (size_t)(4 * j) * L_;
        float v[4];
#pragma unroll
        for (int e = 0; e < 4; ++e) {
            const float* pl = plane + e * L_;
            v[e] = mw4.x * __ldg(pl + mi4.x) + mw4.y * __ldg(pl + mi4.y)
                 + mw4.z * __ldg(pl + mi4.z) + mw4.w * __ldg(pl + mi4.w);
        }
#pragma unroll
        for (int t = 0; t < 2; ++t) {
            unsigned hw = packbf(v[2 * t + 1], v[2 * t]);
            float h0 = __uint_as_float(hw << 16);
            float h1 = __uint_as_float(hw & 0xFFFF0000u);
            unsigned lw = packbf(v[2 * t + 1] - h1, v[2 * t] - h0);
            *(unsigned*)(smem + sa[t])        = hw;
            *(unsigned*)(smem + 2048 + sa[t]) = lw;
        }
#pragma unroll
        for (int i = 0; i < 4; ++i)
            cp16(smem_b + 4096 + (tid + i * 256) * 16,
                 d_Bf + (tid + i * 256) * 4);
        CP_COMMIT();
        CP_WAIT0();
    }
    __syncthreads();

    for (int ch = 0; ch < NCH; ++ch) {
        const int buf = ch & 1;
        const bool more = (ch + 1) < NCH;
        float c0[16];
        if (more) {
            const int nc = ch + 1;
            if ((nc & 15) == 0) {
                int mx = (b * K2_ + (nc >> 4)) * L_ + l0 + px;
                mi4 = d_mi[mx]; mw4 = d_mw[mx];
            }
            const float* plane = xb + (size_t)((nc & 15) * 16 + 4 * j) * L_;
#pragma unroll
            for (int e = 0; e < 4; ++e) {
                const float* pl = plane + e * L_;
                c0[e * 4 + 0] = __ldg(pl + mi4.x);
                c0[e * 4 + 1] = __ldg(pl + mi4.y);
                c0[e * 4 + 2] = __ldg(pl + mi4.z);
                c0[e * 4 + 3] = __ldg(pl + mi4.w);
            }
            const unsigned dstB = smem_b + (buf ^ 1) * BUF_BYTES + 4096;
            const unsigned* srcB = d_Bf + nc * 4096;
#pragma unroll
            for (int i = 0; i < 4; ++i)
                cp16(dstB + (tid + i * 256) * 16, srcB + (tid + i * 256) * 4);
            CP_COMMIT();
        }

        // ---- math on current buffer: 3 passes with fragment reuse ----
        {
            char* Ab = smem + buf * BUF_BYTES;
            uint4 ah[2], al[2];
            uint2 bb[8];
#pragma unroll
            for (int i = 0; i < 2; ++i) ah[i] = *(const uint4*)(Ab + ca[i]);
#pragma unroll
            for (int t = 0; t < 8; ++t) bb[t] = *(const uint2*)(Ab + 4096 + bo[t]);
#pragma unroll
            for (int i = 0; i < 2; ++i)
#pragma unroll
                for (int t = 0; t < 8; ++t)
                    mma_bf16(acc[i][t], (const unsigned*)&ah[i],
                             (const unsigned*)&bb[t]);
#pragma unroll
            for (int i = 0; i < 2; ++i) al[i] = *(const uint4*)(Ab + 2048 + ca[i]);
#pragma unroll
            for (int i = 0; i < 2; ++i)
#pragma unroll
                for (int t = 0; t < 8; ++t)
                    mma_bf16(acc[i][t], (const unsigned*)&al[i],
                             (const unsigned*)&bb[t]);
#pragma unroll
            for (int t = 0; t < 8; ++t) bb[t] = *(const uint2*)(Ab + 12288 + bo[t]);
#pragma unroll
            for (int i = 0; i < 2; ++i)
#pragma unroll
                for (int t = 0; t < 8; ++t)
                    mma_bf16(acc[i][t], (const unsigned*)&ah[i],
                             (const unsigned*)&bb[t]);
        }

        if (more) {
            char* An = smem + (buf ^ 1) * BUF_BYTES;
#pragma unroll
            for (int t = 0; t < 2; ++t) {
                float v0 = mw4.x * c0[(2 * t) * 4 + 0] + mw4.y * c0[(2 * t) * 4 + 1]
                         + mw4.z * c0[(2 * t) * 4 + 2] + mw4.w * c0[(2 * t) * 4 + 3];
                float v1 = mw4.x * c0[(2 * t + 1) * 4 + 0] + mw4.y * c0[(2 * t + 1) * 4 + 1]
                         + mw4.z * c0[(2 * t + 1) * 4 + 2] + mw4.w * c0[(2 * t + 1) * 4 + 3];
                unsigned hw = packbf(v1, v0);
                float h0 = __uint_as_float(hw << 16);
                float h1 = __uint_as_float(hw & 0xFFFF0000u);
                unsigned lw = packbf(v1 - h1, v0 - h0);
                *(unsigned*)(An + sa[t])        = hw;
                *(unsigned*)(An + 2048 + sa[t]) = lw;
            }
        }
        CP_WAIT0();
        __syncthreads();
    }

    // ---- epilogue: relu + direct stores ----
#pragma unroll
    for (int i = 0; i < 2; ++i) {
        int pxg = l0 + ((wid & 1) * 2 + i) * 16 + (lane >> 2);
#pragma unroll
        for (int t = 0; t < 8; ++t) {
            int co = ncol * 64 + t * 8 + 2 * (lane & 3);
            float* o0 = out + ((size_t)(b * COUT + co)) * L_ + pxg;
            float* o1 = o0 + L_;
            o0[0] = fmaxf(acc[i][t][0], 0.0f);
            o1[0] = fmaxf(acc[i][t][1], 0.0f);
            o0[8] = fmaxf(acc[i][t][2], 0.0f);
            o1[8] = fmaxf(acc[i][t][3], 0.0f);
        }
    }
}

// ---------------------------------------------------------------------------
extern "C" void kernel_launch(void* const* d_in, const int* in_sizes, int n_in,
                              void* d_out, int out_size) {
    const float* x   = (const float*)d_in[0];  // [8,256,64,64]
    const float* anc = (const float*)d_in[1];  // [8,4096,5]
    const float* w   = (const float*)d_in[2];  // [256,256,3,3]
    float* out = (float*)d_out;                // [8,256,64,64]

    meta_kernel<<<(B_ * K2_ * L_ + 255) / 256, 256>>>(anc);
    bf_kernel<<<(NCH * 4096 + 255) / 256, 256>>>(w);
    gemm_kernel<<<512, 256>>>(x, out);
}

// round 6
// speedup vs baseline: 4.5398x; 1.3106x over previous
#include <cuda_runtime.h>
#include <cuda_fp16.h>

#define B_    8
#define CIN   256
#define COUT  256
#define H_    64
#define W_    64
#define L_    4096
#define K2_   9
#define NCH   144        // 9 k2 * 16 ci-chunks of 16

// per-buffer smem: Ah 2K | Al 2K | B 8K
#define BUF_BYTES 12288

// Scratch (static __device__ arrays — no runtime allocation)
__device__ int4     d_mi[B_ * K2_ * L_];     // bilinear corner indices [b][k2][l]
__device__ float4   d_mw[B_ * K2_ * L_];     // bilinear corner weights (masked)
__device__ unsigned d_Bf[NCH * 2048];        // fp16 B frags [chunk][tile][lane][reg]

// ---------------------------------------------------------------------------
__device__ __forceinline__ void mma_fp16(float* d, const unsigned* a,
                                         const unsigned* b) {
    asm volatile(
        "mma.sync.aligned.m16n8k16.row.col.f32.f16.f16.f32 "
        "{%0,%1,%2,%3}, {%4,%5,%6,%7}, {%8,%9}, {%0,%1,%2,%3};"
        : "+f"(d[0]), "+f"(d[1]), "+f"(d[2]), "+f"(d[3])
        : "r"(a[0]), "r"(a[1]), "r"(a[2]), "r"(a[3]), "r"(b[0]), "r"(b[1]));
}
__device__ __forceinline__ void cp16(unsigned dst, const void* src) {
    asm volatile("cp.async.cg.shared.global [%0], [%1], 16;"
                 :: "r"(dst), "l"(src));
}
#define CP_COMMIT() asm volatile("cp.async.commit_group;" ::: "memory")
#define CP_WAIT0()  asm volatile("cp.async.wait_group 0;" ::: "memory")

// pack two floats into fp16x2 hi-word and residual lo-word
__device__ __forceinline__ void split16(float v0, float v1,
                                        unsigned& hw, unsigned& lw) {
    __half2 h = __floats2half2_rn(v0, v1);
    float r0 = v0 - __low2float(h);
    float r1 = v1 - __high2float(h);
    __half2 l = __floats2half2_rn(r0, r1);
    hw = *(unsigned*)&h;
    lw = *(unsigned*)&l;
}

// ---------------------------------------------------------------------------
// Kernel 1: bilinear metadata (validated)
// ---------------------------------------------------------------------------
__global__ void meta_kernel(const float* __restrict__ anc) {
    int g = blockIdx.x * blockDim.x + threadIdx.x;
    if (g >= B_ * K2_ * L_) return;
    int l = g % L_, k2 = (g / L_) % K2_, b = g / (L_ * K2_);

    const float* a = anc + (size_t)(b * L_ + l) * 5;
    float xc = a[0] * 0.125f, yc = a[1] * 0.125f;
    float dw = (a[2] * 0.125f) / 3.0f, dh = (a[3] * 0.125f) / 3.0f;
    float s, c;
    sincosf(a[4], &s, &c);
    float fx = (float)(k2 % 3) - 1.0f, fy = (float)(k2 / 3) - 1.0f;
    float xk = dw * fx, yk = dh * fy;
    float px = (c * xk - s * yk) + xc;
    float py = (s * xk + c * yk) + yc;

    float x0f = floorf(px), y0f = floorf(py);
    int x0 = (int)x0f, y0 = (int)y0f;
    float wx1 = px - x0f, wy1 = py - y0f;
    float wx0 = 1.0f - wx1, wy0 = 1.0f - wy1;
    int x1 = x0 + 1, y1 = y0 + 1;
    float vx0 = (x0 >= 0 && x0 < W_) ? 1.f : 0.f;
    float vx1 = (x1 >= 0 && x1 < W_) ? 1.f : 0.f;
    float vy0 = (y0 >= 0 && y0 < H_) ? 1.f : 0.f;
    float vy1 = (y1 >= 0 && y1 < H_) ? 1.f : 0.f;
    int xc0 = min(max(x0, 0), W_ - 1), xc1 = min(max(x1, 0), W_ - 1);
    int yc0 = min(max(y0, 0), H_ - 1), yc1 = min(max(y1, 0), H_ - 1);
    d_mi[g] = make_int4(yc0 * W_ + xc0, yc0 * W_ + xc1,
                        yc1 * W_ + xc0, yc1 * W_ + xc1);
    d_mw[g] = make_float4(wy0 * wx0 * vy0 * vx0, wy0 * wx1 * vy0 * vx1,
                          wy1 * wx0 * vy1 * vx0, wy1 * wx1 * vy1 * vx1);
}

// ---------------------------------------------------------------------------
// Kernel 2: bake B into mma fragment order, single fp16 matrix.
// Word = d_Bf[chunk*2048 + tile*64 + lane*2 + reg]
//   co = tile*8 + lane/4 ; k = 2*(lane&3) + 8*reg ; ci = (chunk&15)*16 + k
// ---------------------------------------------------------------------------
__global__ void bf_kernel(const float* __restrict__ w) {
    int i = blockIdx.x * blockDim.x + threadIdx.x;
    if (i >= NCH * 2048) return;
    int chunk = i >> 11;
    int r2    = i & 2047;
    int tile  = r2 >> 6;
    int lane  = (r2 >> 1) & 31;
    int reg   = r2 & 1;

    int co = tile * 8 + (lane >> 2);
    int kb = 2 * (lane & 3) + 8 * reg;
    int ci = (chunk & 15) * 16 + kb;
    int k2 = chunk >> 4;

    float v0 = w[((size_t)co * CIN + ci) * K2_ + k2];
    float v1 = w[((size_t)co * CIN + ci + 1) * K2_ + k2];
    __half2 h = __floats2half2_rn(v0, v1);
    d_Bf[i] = *(unsigned*)&h;
}

// ---------------------------------------------------------------------------
// Kernel 3: implicit GEMM, mma.sync fp16 2-pass (A split hi/lo, B shared).
//   CTA: M=64 px x N=256 couts, 256 threads (8 warps: 2M x 4N, warp 32x64).
// ---------------------------------------------------------------------------
__global__ __launch_bounds__(256)
void gemm_kernel(const float* __restrict__ x, float* __restrict__ out) {
    __shared__ uint4 smem4[2 * BUF_BYTES / 16];
    char* smem = (char*)smem4;
    const unsigned smem_b = (unsigned)__cvta_generic_to_shared(smem);

    const int tid  = threadIdx.x;
    const int lane = tid & 31;
    const int wid  = tid >> 5;
    const int b    = blockIdx.x >> 6;
    const int l0   = (blockIdx.x & 63) << 6;   // 64-pixel tiles
    const int px   = tid & 63;
    const int j    = tid >> 6;                 // ci quartet (4 ci each)

    // --- producer A STS byte offsets (2 k-pairs: p = 2j, 2j+1) ---
    const int r  = px & 15, mt = px >> 4;
    const int rs = (r >> 1) & 3;
    int sa[2];
#pragma unroll
    for (int t = 0; t < 2; ++t) {
        int p = 2 * j + t;
        int g = mt * 32 + ((((r & 7) << 2) | (p & 3)) ^ rs);
        sa[t] = g * 16 + (2 * (p >= 4) + (r >= 8)) * 4;
    }
    // --- consumer A fragment offsets (2 m16 tiles per warp) ---
    int ca[2];
#pragma unroll
    for (int i = 0; i < 2; ++i) {
        int mtc = (wid & 1) * 2 + i;
        ca[i] = (mtc * 32 + (lane ^ ((lane >> 3) & 3))) * 16;
    }
    // --- consumer B fragment offsets (8 n8 tiles per warp) ---
    const int ncol = wid >> 1;
    int bo[8];
#pragma unroll
    for (int t = 0; t < 8; ++t)
        bo[t] = (((ncol * 8 + t) * 64) + lane * 2) << 2;

    float acc[2][8][4];
#pragma unroll
    for (int i = 0; i < 2; ++i)
#pragma unroll
        for (int t = 0; t < 8; ++t)
#pragma unroll
            for (int q = 0; q < 4; ++q) acc[i][t][q] = 0.0f;

    const float* xb = x + (size_t)b * CIN * L_;
    int4 mi4; float4 mw4;
    {
        int mx = (b * K2_) * L_ + l0 + px;
        mi4 = d_mi[mx]; mw4 = d_mw[mx];
    }

    // ---- prologue: fill buffer 0 with chunk 0 ----
    {
        const float* plane = xb + (size_t)(4 * j) * L_;
        float v[4];
#pragma unroll
        for (int e = 0; e < 4; ++e) {
            const float* pl = plane + e * L_;
            v[e] = mw4.x * __ldg(pl + mi4.x) + mw4.y * __ldg(pl + mi4.y)
                 + mw4.z * __ldg(pl + mi4.z) + mw4.w * __ldg(pl + mi4.w);
        }
#pragma unroll
        for (int t = 0; t < 2; ++t) {
            unsigned hw, lw;
            split16(v[2 * t], v[2 * t + 1], hw, lw);
            *(unsigned*)(smem + sa[t])        = hw;
            *(unsigned*)(smem + 2048 + sa[t]) = lw;
        }
#pragma unroll
        for (int i = 0; i < 2; ++i)
            cp16(smem_b + 4096 + (tid + i * 256) * 16,
                 d_Bf + (tid + i * 256) * 4);
        CP_COMMIT();
        CP_WAIT0();
    }
    __syncthreads();

    for (int ch = 0; ch < NCH; ++ch) {
        const int buf = ch & 1;
        const bool more = (ch + 1) < NCH;
        float c0[16];
        if (more) {
            const int nc = ch + 1;
            if ((nc & 15) == 0) {
                int mx = (b * K2_ + (nc >> 4)) * L_ + l0 + px;
                mi4 = d_mi[mx]; mw4 = d_mw[mx];
            }
            const float* plane = xb + (size_t)((nc & 15) * 16 + 4 * j) * L_;
#pragma unroll
            for (int e = 0; e < 4; ++e) {
                const float* pl = plane + e * L_;
                c0[e * 4 + 0] = __ldg(pl + mi4.x);
                c0[e * 4 + 1] = __ldg(pl + mi4.y);
                c0[e * 4 + 2] = __ldg(pl + mi4.z);
                c0[e * 4 + 3] = __ldg(pl + mi4.w);
            }
            const unsigned dstB = smem_b + (buf ^ 1) * BUF_BYTES + 4096;
            const unsigned* srcB = d_Bf + nc * 2048;
#pragma unroll
            for (int i = 0; i < 2; ++i)
                cp16(dstB + (tid + i * 256) * 16, srcB + (tid + i * 256) * 4);
            CP_COMMIT();
        }

        // ---- math: 2 passes sharing B fragments ----
        {
            char* Ab = smem + buf * BUF_BYTES;
            uint4 ah[2], al[2];
            uint2 bb[8];
#pragma unroll
            for (int i = 0; i < 2; ++i) ah[i] = *(const uint4*)(Ab + ca[i]);
#pragma unroll
            for (int t = 0; t < 8; ++t) bb[t] = *(const uint2*)(Ab + 4096 + bo[t]);
#pragma unroll
            for (int i = 0; i < 2; ++i)
#pragma unroll
                for (int t = 0; t < 8; ++t)
                    mma_fp16(acc[i][t], (const unsigned*)&ah[i],
                             (const unsigned*)&bb[t]);
#pragma unroll
            for (int i = 0; i < 2; ++i) al[i] = *(const uint4*)(Ab + 2048 + ca[i]);
#pragma unroll
            for (int i = 0; i < 2; ++i)
#pragma unroll
                for (int t = 0; t < 8; ++t)
                    mma_fp16(acc[i][t], (const unsigned*)&al[i],
                             (const unsigned*)&bb[t]);
        }

        if (more) {
            char* An = smem + (buf ^ 1) * BUF_BYTES;
#pragma unroll
            for (int t = 0; t < 2; ++t) {
                float v0 = mw4.x * c0[(2 * t) * 4 + 0] + mw4.y * c0[(2 * t) * 4 + 1]
                         + mw4.z * c0[(2 * t) * 4 + 2] + mw4.w * c0[(2 * t) * 4 + 3];
                float v1 = mw4.x * c0[(2 * t + 1) * 4 + 0] + mw4.y * c0[(2 * t + 1) * 4 + 1]
                         + mw4.z * c0[(2 * t + 1) * 4 + 2] + mw4.w * c0[(2 * t + 1) * 4 + 3];
                unsigned hw, lw;
                split16(v0, v1, hw, lw);
                *(unsigned*)(An + sa[t])        = hw;
                *(unsigned*)(An + 2048 + sa[t]) = lw;
            }
        }
        CP_WAIT0();
        __syncthreads();
    }

    // ---- epilogue: relu + direct stores ----
#pragma unroll
    for (int i = 0; i < 2; ++i) {
        int pxg = l0 + ((wid & 1) * 2 + i) * 16 + (lane >> 2);
#pragma unroll
        for (int t = 0; t < 8; ++t) {
            int co = ncol * 64 + t * 8 + 2 * (lane & 3);
            float* o0 = out + ((size_t)(b * COUT + co)) * L_ + pxg;
            float* o1 = o0 + L_;
            o0[0] = fmaxf(acc[i][t][0], 0.0f);
            o1[0] = fmaxf(acc[i][t][1], 0.0f);
            o0[8] = fmaxf(acc[i][t][2], 0.0f);
            o1[8] = fmaxf(acc[i][t][3], 0.0f);
        }
    }
}

// ---------------------------------------------------------------------------
extern "C" void kernel_launch(void* const* d_in, const int* in_sizes, int n_in,
                              void* d_out, int out_size) {
    const float* x   = (const float*)d_in[0];  // [8,256,64,64]
    const float* anc = (const float*)d_in[1];  // [8,4096,5]
    const float* w   = (const float*)d_in[2];  // [256,256,3,3]
    float* out = (float*)d_out;                // [8,256,64,64]

    meta_kernel<<<(B_ * K2_ * L_ + 255) / 256, 256>>>(anc);
    bf_kernel<<<(NCH * 2048 + 255) / 256, 256>>>(w);
    gemm_kernel<<<512, 256>>>(x, out);
}

// round 7
// speedup vs baseline: 5.5961x; 1.2327x over previous
#include <cuda_runtime.h>
#include <cuda_fp16.h>

#define B_    8
#define CIN   256
#define COUT  256
#define H_    64
#define W_    64
#define L_    4096
#define K2_   9
#define NCH   144        // 9 k2 * 16 ci-chunks of 16

// per-buffer smem: A 2K | B 8K
#define BUF_BYTES 10240

// Scratch (static __device__ arrays — no runtime allocation)
__device__ int4     d_mi[B_ * K2_ * L_];     // bilinear corner indices [b][k2][l]
__device__ float4   d_mw[B_ * K2_ * L_];     // bilinear corner weights (masked)
__device__ unsigned d_Bf[NCH * 2048];        // fp16 B frags [chunk][tile][lane][reg]

// ---------------------------------------------------------------------------
__device__ __forceinline__ void mma_fp16(float* d, const unsigned* a,
                                         const unsigned* b) {
    asm volatile(
        "mma.sync.aligned.m16n8k16.row.col.f32.f16.f16.f32 "
        "{%0,%1,%2,%3}, {%4,%5,%6,%7}, {%8,%9}, {%0,%1,%2,%3};"
        : "+f"(d[0]), "+f"(d[1]), "+f"(d[2]), "+f"(d[3])
        : "r"(a[0]), "r"(a[1]), "r"(a[2]), "r"(a[3]), "r"(b[0]), "r"(b[1]));
}
__device__ __forceinline__ void cp16(unsigned dst, const void* src) {
    asm volatile("cp.async.cg.shared.global [%0], [%1], 16;"
                 :: "r"(dst), "l"(src));
}
#define CP_COMMIT() asm volatile("cp.async.commit_group;" ::: "memory")
#define CP_WAIT0()  asm volatile("cp.async.wait_group 0;" ::: "memory")

__device__ __forceinline__ unsigned pack16(float v0, float v1) {
    __half2 h = __floats2half2_rn(v0, v1);
    return *(unsigned*)&h;
}

// ---------------------------------------------------------------------------
// Kernel 1: bilinear metadata (validated)
// ---------------------------------------------------------------------------
__global__ void meta_kernel(const float* __restrict__ anc) {
    int g = blockIdx.x * blockDim.x + threadIdx.x;
    if (g >= B_ * K2_ * L_) return;
    int l = g % L_, k2 = (g / L_) % K2_, b = g / (L_ * K2_);

    const float* a = anc + (size_t)(b * L_ + l) * 5;
    float xc = a[0] * 0.125f, yc = a[1] * 0.125f;
    float dw = (a[2] * 0.125f) / 3.0f, dh = (a[3] * 0.125f) / 3.0f;
    float s, c;
    sincosf(a[4], &s, &c);
    float fx = (float)(k2 % 3) - 1.0f, fy = (float)(k2 / 3) - 1.0f;
    float xk = dw * fx, yk = dh * fy;
    float px = (c * xk - s * yk) + xc;
    float py = (s * xk + c * yk) + yc;

    float x0f = floorf(px), y0f = floorf(py);
    int x0 = (int)x0f, y0 = (int)y0f;
    float wx1 = px - x0f, wy1 = py - y0f;
    float wx0 = 1.0f - wx1, wy0 = 1.0f - wy1;
    int x1 = x0 + 1, y1 = y0 + 1;
    float vx0 = (x0 >= 0 && x0 < W_) ? 1.f : 0.f;
    float vx1 = (x1 >= 0 && x1 < W_) ? 1.f : 0.f;
    float vy0 = (y0 >= 0 && y0 < H_) ? 1.f : 0.f;
    float vy1 = (y1 >= 0 && y1 < H_) ? 1.f : 0.f;
    int xc0 = min(max(x0, 0), W_ - 1), xc1 = min(max(x1, 0), W_ - 1);
    int yc0 = min(max(y0, 0), H_ - 1), yc1 = min(max(y1, 0), H_ - 1);
    d_mi[g] = make_int4(yc0 * W_ + xc0, yc0 * W_ + xc1,
                        yc1 * W_ + xc0, yc1 * W_ + xc1);
    d_mw[g] = make_float4(wy0 * wx0 * vy0 * vx0, wy0 * wx1 * vy0 * vx1,
                          wy1 * wx0 * vy1 * vx0, wy1 * wx1 * vy1 * vx1);
}

// ---------------------------------------------------------------------------
// Kernel 2: bake B into mma fragment order, single fp16 matrix (validated).
// ---------------------------------------------------------------------------
__global__ void bf_kernel(const float* __restrict__ w) {
    int i = blockIdx.x * blockDim.x + threadIdx.x;
    if (i >= NCH * 2048) return;
    int chunk = i >> 11;
    int r2    = i & 2047;
    int tile  = r2 >> 6;
    int lane  = (r2 >> 1) & 31;
    int reg   = r2 & 1;

    int co = tile * 8 + (lane >> 2);
    int kb = 2 * (lane & 3) + 8 * reg;
    int ci = (chunk & 15) * 16 + kb;
    int k2 = chunk >> 4;

    float v0 = w[((size_t)co * CIN + ci) * K2_ + k2];
    float v1 = w[((size_t)co * CIN + ci + 1) * K2_ + k2];
    d_Bf[i] = pack16(v0, v1);
}

// ---------------------------------------------------------------------------
// Kernel 3: implicit GEMM, mma.sync fp16 single pass.
//   CTA: M=64 px x N=256 couts, 256 threads (8 warps: 2M x 4N, warp 32x64).
// ---------------------------------------------------------------------------
__global__ __launch_bounds__(256, 2)
void gemm_kernel(const float* __restrict__ x, float* __restrict__ out) {
    __shared__ uint4 smem4[2 * BUF_BYTES / 16];
    char* smem = (char*)smem4;
    const unsigned smem_b = (unsigned)__cvta_generic_to_shared(smem);

    const int tid  = threadIdx.x;
    const int lane = tid & 31;
    const int wid  = tid >> 5;
    const int b    = blockIdx.x >> 6;
    const int l0   = (blockIdx.x & 63) << 6;   // 64-pixel tiles
    const int px   = tid & 63;
    const int j    = tid >> 6;                 // ci quartet (4 ci each)

    // --- producer A STS byte offsets (2 k-pairs: p = 2j, 2j+1) ---
    const int r  = px & 15, mt = px >> 4;
    const int rs = (r >> 1) & 3;
    int sa[2];
#pragma unroll
    for (int t = 0; t < 2; ++t) {
        int p = 2 * j + t;
        int g = mt * 32 + ((((r & 7) << 2) | (p & 3)) ^ rs);
        sa[t] = g * 16 + (2 * (p >= 4) + (r >= 8)) * 4;
    }
    // --- consumer A fragment offsets (2 m16 tiles per warp) ---
    int ca[2];
#pragma unroll
    for (int i = 0; i < 2; ++i) {
        int mtc = (wid & 1) * 2 + i;
        ca[i] = (mtc * 32 + (lane ^ ((lane >> 3) & 3))) * 16;
    }
    // --- consumer B fragment offsets (8 n8 tiles per warp) ---
    const int ncol = wid >> 1;
    int bo[8];
#pragma unroll
    for (int t = 0; t < 8; ++t)
        bo[t] = (((ncol * 8 + t) * 64) + lane * 2) << 2;

    float acc[2][8][4];
#pragma unroll
    for (int i = 0; i < 2; ++i)
#pragma unroll
        for (int t = 0; t < 8; ++t)
#pragma unroll
            for (int q = 0; q < 4; ++q) acc[i][t][q] = 0.0f;

    const float* xb = x + (size_t)b * CIN * L_;
    int4 mi4; float4 mw4;
    {
        int mx = (b * K2_) * L_ + l0 + px;
        mi4 = d_mi[mx]; mw4 = d_mw[mx];
    }

    // ---- prologue: fill buffer 0 with chunk 0 ----
    {
        const float* plane = xb + (size_t)(4 * j) * L_;
        float v[4];
#pragma unroll
        for (int e = 0; e < 4; ++e) {
            const float* pl = plane + e * L_;
            v[e] = mw4.x * __ldg(pl + mi4.x) + mw4.y * __ldg(pl + mi4.y)
                 + mw4.z * __ldg(pl + mi4.z) + mw4.w * __ldg(pl + mi4.w);
        }
#pragma unroll
        for (int t = 0; t < 2; ++t)
            *(unsigned*)(smem + sa[t]) = pack16(v[2 * t], v[2 * t + 1]);
#pragma unroll
        for (int i = 0; i < 2; ++i)
            cp16(smem_b + 2048 + (tid + i * 256) * 16,
                 d_Bf + (tid + i * 256) * 4);
        CP_COMMIT();
        CP_WAIT0();
    }
    __syncthreads();

    for (int ch = 0; ch < NCH; ++ch) {
        const int buf = ch & 1;
        const bool more = (ch + 1) < NCH;
        float c0[16];
        if (more) {
            const int nc = ch + 1;
            if ((nc & 15) == 0) {
                int mx = (b * K2_ + (nc >> 4)) * L_ + l0 + px;
                mi4 = d_mi[mx]; mw4 = d_mw[mx];
            }
            const float* plane = xb + (size_t)((nc & 15) * 16 + 4 * j) * L_;
#pragma unroll
            for (int e = 0; e < 4; ++e) {
                const float* pl = plane + e * L_;
                c0[e * 4 + 0] = __ldg(pl + mi4.x);
                c0[e * 4 + 1] = __ldg(pl + mi4.y);
                c0[e * 4 + 2] = __ldg(pl + mi4.z);
                c0[e * 4 + 3] = __ldg(pl + mi4.w);
            }
            const unsigned dstB = smem_b + (buf ^ 1) * BUF_BYTES + 2048;
            const unsigned* srcB = d_Bf + nc * 2048;
#pragma unroll
            for (int i = 0; i < 2; ++i)
                cp16(dstB + (tid + i * 256) * 16, srcB + (tid + i * 256) * 4);
            CP_COMMIT();
        }

        // ---- math: single fp16 pass ----
        {
            char* Ab = smem + buf * BUF_BYTES;
            uint4 ah[2];
            uint2 bb[8];
#pragma unroll
            for (int i = 0; i < 2; ++i) ah[i] = *(const uint4*)(Ab + ca[i]);
#pragma unroll
            for (int t = 0; t < 8; ++t) bb[t] = *(const uint2*)(Ab + 2048 + bo[t]);
#pragma unroll
            for (int i = 0; i < 2; ++i)
#pragma unroll
                for (int t = 0; t < 8; ++t)
                    mma_fp16(acc[i][t], (const unsigned*)&ah[i],
                             (const unsigned*)&bb[t]);
        }

        if (more) {
            char* An = smem + (buf ^ 1) * BUF_BYTES;
#pragma unroll
            for (int t = 0; t < 2; ++t) {
                float v0 = mw4.x * c0[(2 * t) * 4 + 0] + mw4.y * c0[(2 * t) * 4 + 1]
                         + mw4.z * c0[(2 * t) * 4 + 2] + mw4.w * c0[(2 * t) * 4 + 3];
                float v1 = mw4.x * c0[(2 * t + 1) * 4 + 0] + mw4.y * c0[(2 * t + 1) * 4 + 1]
                         + mw4.z * c0[(2 * t + 1) * 4 + 2] + mw4.w * c0[(2 * t + 1) * 4 + 3];
                *(unsigned*)(An + sa[t]) = pack16(v0, v1);
            }
        }
        CP_WAIT0();
        __syncthreads();
    }

    // ---- epilogue: relu + direct stores ----
#pragma unroll
    for (int i = 0; i < 2; ++i) {
        int pxg = l0 + ((wid & 1) * 2 + i) * 16 + (lane >> 2);
#pragma unroll
        for (int t = 0; t < 8; ++t) {
            int co = ncol * 64 + t * 8 + 2 * (lane & 3);
            float* o0 = out + ((size_t)(b * COUT + co)) * L_ + pxg;
            float* o1 = o0 + L_;
            o0[0] = fmaxf(acc[i][t][0], 0.0f);
            o1[0] = fmaxf(acc[i][t][1], 0.0f);
            o0[8] = fmaxf(acc[i][t][2], 0.0f);
            o1[8] = fmaxf(acc[i][t][3], 0.0f);
        }
    }
}

// ---------------------------------------------------------------------------
extern "C" void kernel_launch(void* const* d_in, const int* in_sizes, int n_in,
                              void* d_out, int out_size) {
    const float* x   = (const float*)d_in[0];  // [8,256,64,64]
    const float* anc = (const float*)d_in[1];  // [8,4096,5]
    const float* w   = (const float*)d_in[2];  // [256,256,3,3]
    float* out = (float*)d_out;                // [8,256,64,64]

    meta_kernel<<<(B_ * K2_ * L_ + 255) / 256, 256>>>(anc);
    bf_kernel<<<(NCH * 2048 + 255) / 256, 256>>>(w);
    gemm_kernel<<<512, 256>>>(x, out);
}

// round 8
// speedup vs baseline: 7.6556x; 1.3680x over previous
#include <cuda_runtime.h>
#include <cuda_fp16.h>

#define B_    8
#define CIN   256
#define COUT  256
#define H_    64
#define W_    64
#define L_    4096
#define K2_   9
#define NCH   144        // 9 k2 * 16 ci-chunks of 16

// per-buffer smem: A 2K | B 8K
#define BUF_BYTES 10240

// Scratch (static __device__ arrays — no runtime allocation)
__device__ int4     d_mi[B_ * K2_ * L_];     // bilinear corner indices [b][k2][l]
__device__ float4   d_mw[B_ * K2_ * L_];     // bilinear corner weights (masked)
__device__ unsigned d_Bf[NCH * 2048];        // fp16 B frags [chunk][tile][lane][reg]
__device__ float    d_xT[(size_t)B_ * L_ * CIN];  // x transposed to [b][pixel][ci]

// ---------------------------------------------------------------------------
__device__ __forceinline__ void mma_fp16(float* d, const unsigned* a,
                                         const unsigned* b) {
    asm volatile(
        "mma.sync.aligned.m16n8k16.row.col.f32.f16.f16.f32 "
        "{%0,%1,%2,%3}, {%4,%5,%6,%7}, {%8,%9}, {%0,%1,%2,%3};"
        : "+f"(d[0]), "+f"(d[1]), "+f"(d[2]), "+f"(d[3])
        : "r"(a[0]), "r"(a[1]), "r"(a[2]), "r"(a[3]), "r"(b[0]), "r"(b[1]));
}
__device__ __forceinline__ void cp16(unsigned dst, const void* src) {
    asm volatile("cp.async.cg.shared.global [%0], [%1], 16;"
                 :: "r"(dst), "l"(src));
}
#define CP_COMMIT() asm volatile("cp.async.commit_group;" ::: "memory")
#define CP_WAIT0()  asm volatile("cp.async.wait_group 0;" ::: "memory")

__device__ __forceinline__ unsigned pack16(float v0, float v1) {
    __half2 h = __floats2half2_rn(v0, v1);
    return *(unsigned*)&h;
}

// ---------------------------------------------------------------------------
// Kernel 0: transpose x NCHW -> NHWC ([b][ci][l] -> [b][l][ci])
// ---------------------------------------------------------------------------
__global__ void tr_kernel(const float* __restrict__ x) {
    __shared__ float t[32][33];
    const int tx = threadIdx.x & 31, ty = threadIdx.x >> 5;
    const int l0 = blockIdx.x << 5;       // 128 l-tiles
    const int c0 = blockIdx.y << 5;       // 8 ci-tiles
    const int b  = blockIdx.z;
    const float* xb = x + ((size_t)b * CIN + c0) * L_ + l0;
#pragma unroll
    for (int i = 0; i < 4; ++i)
        t[ty + i * 8][tx] = xb[(size_t)(ty + i * 8) * L_ + tx];  // t[ci][l]
    __syncthreads();
    float* ob = d_xT + ((size_t)b * L_ + l0) * CIN + c0;
#pragma unroll
    for (int i = 0; i < 4; ++i)
        ob[(size_t)(ty + i * 8) * CIN + tx] = t[tx][ty + i * 8];
}

// ---------------------------------------------------------------------------
// Kernel 1: bilinear metadata (validated)
// ---------------------------------------------------------------------------
__global__ void meta_kernel(const float* __restrict__ anc) {
    int g = blockIdx.x * blockDim.x + threadIdx.x;
    if (g >= B_ * K2_ * L_) return;
    int l = g % L_, k2 = (g / L_) % K2_, b = g / (L_ * K2_);

    const float* a = anc + (size_t)(b * L_ + l) * 5;
    float xc = a[0] * 0.125f, yc = a[1] * 0.125f;
    float dw = (a[2] * 0.125f) / 3.0f, dh = (a[3] * 0.125f) / 3.0f;
    float s, c;
    sincosf(a[4], &s, &c);
    float fx = (float)(k2 % 3) - 1.0f, fy = (float)(k2 / 3) - 1.0f;
    float xk = dw * fx, yk = dh * fy;
    float px = (c * xk - s * yk) + xc;
    float py = (s * xk + c * yk) + yc;

    float x0f = floorf(px), y0f = floorf(py);
    int x0 = (int)x0f, y0 = (int)y0f;
    float wx1 = px - x0f, wy1 = py - y0f;
    float wx0 = 1.0f - wx1, wy0 = 1.0f - wy1;
    int x1 = x0 + 1, y1 = y0 + 1;
    float vx0 = (x0 >= 0 && x0 < W_) ? 1.f : 0.f;
    float vx1 = (x1 >= 0 && x1 < W_) ? 1.f : 0.f;
    float vy0 = (y0 >= 0 && y0 < H_) ? 1.f : 0.f;
    float vy1 = (y1 >= 0 && y1 < H_) ? 1.f : 0.f;
    int xc0 = min(max(x0, 0), W_ - 1), xc1 = min(max(x1, 0), W_ - 1);
    int yc0 = min(max(y0, 0), H_ - 1), yc1 = min(max(y1, 0), H_ - 1);
    d_mi[g] = make_int4(yc0 * W_ + xc0, yc0 * W_ + xc1,
                        yc1 * W_ + xc0, yc1 * W_ + xc1);
    d_mw[g] = make_float4(wy0 * wx0 * vy0 * vx0, wy0 * wx1 * vy0 * vx1,
                          wy1 * wx0 * vy1 * vx0, wy1 * wx1 * vy1 * vx1);
}

// ---------------------------------------------------------------------------
// Kernel 2: bake B into mma fragment order, single fp16 matrix (validated).
// ---------------------------------------------------------------------------
__global__ void bf_kernel(const float* __restrict__ w) {
    int i = blockIdx.x * blockDim.x + threadIdx.x;
    if (i >= NCH * 2048) return;
    int chunk = i >> 11;
    int r2    = i & 2047;
    int tile  = r2 >> 6;
    int lane  = (r2 >> 1) & 31;
    int reg   = r2 & 1;

    int co = tile * 8 + (lane >> 2);
    int kb = 2 * (lane & 3) + 8 * reg;
    int ci = (chunk & 15) * 16 + kb;
    int k2 = chunk >> 4;

    float v0 = w[((size_t)co * CIN + ci) * K2_ + k2];
    float v1 = w[((size_t)co * CIN + ci + 1) * K2_ + k2];
    d_Bf[i] = pack16(v0, v1);
}

// ---------------------------------------------------------------------------
// Kernel 3: implicit GEMM, mma.sync fp16, NHWC coalesced gather.
//   CTA: M=64 px x N=256 couts, 256 threads (8 warps: 2M x 4N, warp 32x64).
//   Thread (q=tid&3, pxl=tid>>2) gathers ci-quartet 4q..4q+3 of pixel pxl
//   as 4 contiguous float4 corner loads.
// ---------------------------------------------------------------------------
__global__ __launch_bounds__(256, 2)
void gemm_kernel(float* __restrict__ out) {
    __shared__ uint4 smem4[2 * BUF_BYTES / 16];
    char* smem = (char*)smem4;
    const unsigned smem_b = (unsigned)__cvta_generic_to_shared(smem);

    const int tid  = threadIdx.x;
    const int lane = tid & 31;
    const int wid  = tid >> 5;
    const int b    = blockIdx.x >> 6;
    const int l0   = (blockIdx.x & 63) << 6;   // 64-pixel tiles
    const int q    = tid & 3;                  // ci quartet within chunk
    const int pxl  = tid >> 2;                 // pixel within tile (0..63)

    // --- producer A STS byte offsets (k-pairs p = 2q, 2q+1 of pixel pxl) ---
    const int r  = pxl & 15, mt = pxl >> 4;
    const int rs = (r >> 1) & 3;
    int sa[2];
#pragma unroll
    for (int t = 0; t < 2; ++t) {
        int p = 2 * q + t;
        int g = mt * 32 + ((((r & 7) << 2) | (p & 3)) ^ rs);
        sa[t] = g * 16 + (2 * (p >= 4) + (r >= 8)) * 4;
    }
    // --- consumer A fragment offsets (2 m16 tiles per warp) ---
    int ca[2];
#pragma unroll
    for (int i = 0; i < 2; ++i) {
        int mtc = (wid & 1) * 2 + i;
        ca[i] = (mtc * 32 + (lane ^ ((lane >> 3) & 3))) * 16;
    }
    // --- consumer B fragment offsets (8 n8 tiles per warp) ---
    const int ncol = wid >> 1;
    int bo[8];
#pragma unroll
    for (int t = 0; t < 8; ++t)
        bo[t] = (((ncol * 8 + t) * 64) + lane * 2) << 2;

    float acc[2][8][4];
#pragma unroll
    for (int i = 0; i < 2; ++i)
#pragma unroll
        for (int t = 0; t < 8; ++t)
#pragma unroll
            for (int w0 = 0; w0 < 4; ++w0) acc[i][t][w0] = 0.0f;

    const float* xTb = d_xT + (size_t)b * L_ * CIN;
    int4 mi4; float4 mw4;
    {
        int mx = (b * K2_) * L_ + l0 + pxl;
        mi4 = d_mi[mx]; mw4 = d_mw[mx];
    }

    // ---- prologue: fill buffer 0 with chunk 0 ----
    {
        const float* base = xTb + 4 * q;
        float4 g0 = __ldg((const float4*)(base + ((size_t)mi4.x << 8)));
        float4 g1 = __ldg((const float4*)(base + ((size_t)mi4.y << 8)));
        float4 g2 = __ldg((const float4*)(base + ((size_t)mi4.z << 8)));
        float4 g3 = __ldg((const float4*)(base + ((size_t)mi4.w << 8)));
        float v0 = mw4.x * g0.x + mw4.y * g1.x + mw4.z * g2.x + mw4.w * g3.x;
        float v1 = mw4.x * g0.y + mw4.y * g1.y + mw4.z * g2.y + mw4.w * g3.y;
        float v2 = mw4.x * g0.z + mw4.y * g1.z + mw4.z * g2.z + mw4.w * g3.z;
        float v3 = mw4.x * g0.w + mw4.y * g1.w + mw4.z * g2.w + mw4.w * g3.w;
        *(unsigned*)(smem + sa[0]) = pack16(v0, v1);
        *(unsigned*)(smem + sa[1]) = pack16(v2, v3);
#pragma unroll
        for (int i = 0; i < 2; ++i)
            cp16(smem_b + 2048 + (tid + i * 256) * 16,
                 d_Bf + (tid + i * 256) * 4);
        CP_COMMIT();
        CP_WAIT0();
    }
    __syncthreads();

    for (int ch = 0; ch < NCH; ++ch) {
        const int buf = ch & 1;
        const bool more = (ch + 1) < NCH;
        float4 g0, g1, g2, g3;
        if (more) {
            const int nc = ch + 1;
            if ((nc & 15) == 0) {
                int mx = (b * K2_ + (nc >> 4)) * L_ + l0 + pxl;
                mi4 = d_mi[mx]; mw4 = d_mw[mx];
            }
            const float* base = xTb + (nc & 15) * 16 + 4 * q;
            g0 = __ldg((const float4*)(base + ((size_t)mi4.x << 8)));
            g1 = __ldg((const float4*)(base + ((size_t)mi4.y << 8)));
            g2 = __ldg((const float4*)(base + ((size_t)mi4.z << 8)));
            g3 = __ldg((const float4*)(base + ((size_t)mi4.w << 8)));
            const unsigned dstB = smem_b + (buf ^ 1) * BUF_BYTES + 2048;
            const unsigned* srcB = d_Bf + nc * 2048;
#pragma unroll
            for (int i = 0; i < 2; ++i)
                cp16(dstB + (tid + i * 256) * 16, srcB + (tid + i * 256) * 4);
            CP_COMMIT();
        }

        // ---- math: single fp16 pass ----
        {
            char* Ab = smem + buf * BUF_BYTES;
            uint4 ah[2];
            uint2 bb[8];
#pragma unroll
            for (int i = 0; i < 2; ++i) ah[i] = *(const uint4*)(Ab + ca[i]);
#pragma unroll
            for (int t = 0; t < 8; ++t) bb[t] = *(const uint2*)(Ab + 2048 + bo[t]);
#pragma unroll
            for (int i = 0; i < 2; ++i)
#pragma unroll
                for (int t = 0; t < 8; ++t)
                    mma_fp16(acc[i][t], (const unsigned*)&ah[i],
                             (const unsigned*)&bb[t]);
        }

        if (more) {
            char* An = smem + (buf ^ 1) * BUF_BYTES;
            float v0 = mw4.x * g0.x + mw4.y * g1.x + mw4.z * g2.x + mw4.w * g3.x;
            float v1 = mw4.x * g0.y + mw4.y * g1.y + mw4.z * g2.y + mw4.w * g3.y;
            float v2 = mw4.x * g0.z + mw4.y * g1.z + mw4.z * g2.z + mw4.w * g3.z;
            float v3 = mw4.x * g0.w + mw4.y * g1.w + mw4.z * g2.w + mw4.w * g3.w;
            *(unsigned*)(An + sa[0]) = pack16(v0, v1);
            *(unsigned*)(An + sa[1]) = pack16(v2, v3);
        }
        CP_WAIT0();
        __syncthreads();
    }

    // ---- epilogue: relu + direct stores ----
#pragma unroll
    for (int i = 0; i < 2; ++i) {
        int pxg = l0 + ((wid & 1) * 2 + i) * 16 + (lane >> 2);
#pragma unroll
        for (int t = 0; t < 8; ++t) {
            int co = ncol * 64 + t * 8 + 2 * (lane & 3);
            float* o0 = out + ((size_t)(b * COUT + co)) * L_ + pxg;
            float* o1 = o0 + L_;
            o0[0] = fmaxf(acc[i][t][0], 0.0f);
            o1[0] = fmaxf(acc[i][t][1], 0.0f);
            o0[8] = fmaxf(acc[i][t][2], 0.0f);
            o1[8] = fmaxf(acc[i][t][3], 0.0f);
        }
    }
}

// ---------------------------------------------------------------------------
extern "C" void kernel_launch(void* const* d_in, const int* in_sizes, int n_in,
                              void* d_out, int out_size) {
    const float* x   = (const float*)d_in[0];  // [8,256,64,64]
    const float* anc = (const float*)d_in[1];  // [8,4096,5]
    const float* w   = (const float*)d_in[2];  // [256,256,3,3]
    float* out = (float*)d_out;                // [8,256,64,64]

    tr_kernel<<<dim3(128, 8, 8), 256>>>(x);
    meta_kernel<<<(B_ * K2_ * L_ + 255) / 256, 256>>>(anc);
    bf_kernel<<<(NCH * 2048 + 255) / 256, 256>>>(w);
    gemm_kernel<<<512, 256>>>(out);
}

// round 9
// speedup vs baseline: 8.2390x; 1.0762x over previous
#include <cuda_runtime.h>
#include <cuda_fp16.h>

#define B_    8
#define CIN   256
#define COUT  256
#define H_    64
#define W_    64
#define L_    4096
#define K2_   9
#define NCH16 144        // 9 k2 * 16 ci-chunks of 16 (B-bake granularity)
#define NCH   72         // 9 k2 * 8  ci-chunks of 32 (GEMM granularity)

// per-buffer smem: A 4K (2 sub x 2K) | B 16K (2 sub x 8K)
#define BUF_BYTES 20480

// Scratch (static __device__ arrays — no runtime allocation)
__device__ int4     d_mi[B_ * K2_ * L_];     // bilinear corner indices [b][k2][l]
__device__ float4   d_mw[B_ * K2_ * L_];     // bilinear corner weights (masked)
__device__ unsigned d_Bf[NCH16 * 2048];      // fp16 B frags [chunk16][tile][lane][reg]
__device__ float    d_xT[(size_t)B_ * L_ * CIN];  // x transposed to [b][pixel][ci]

// ---------------------------------------------------------------------------
__device__ __forceinline__ void mma_fp16(float* d, const unsigned* a,
                                         const unsigned* b) {
    asm volatile(
        "mma.sync.aligned.m16n8k16.row.col.f32.f16.f16.f32 "
        "{%0,%1,%2,%3}, {%4,%5,%6,%7}, {%8,%9}, {%0,%1,%2,%3};"
        : "+f"(d[0]), "+f"(d[1]), "+f"(d[2]), "+f"(d[3])
        : "r"(a[0]), "r"(a[1]), "r"(a[2]), "r"(a[3]), "r"(b[0]), "r"(b[1]));
}
__device__ __forceinline__ void cp16(unsigned dst, const void* src) {
    asm volatile("cp.async.cg.shared.global [%0], [%1], 16;"
                 :: "r"(dst), "l"(src));
}
#define CP_COMMIT() asm volatile("cp.async.commit_group;" ::: "memory")
#define CP_WAIT0()  asm volatile("cp.async.wait_group 0;" ::: "memory")

__device__ __forceinline__ unsigned pack16(float v0, float v1) {
    __half2 h = __floats2half2_rn(v0, v1);
    return *(unsigned*)&h;
}

// ---------------------------------------------------------------------------
// Kernel 0: transpose x NCHW -> NHWC ([b][ci][l] -> [b][l][ci])
// ---------------------------------------------------------------------------
__global__ void tr_kernel(const float* __restrict__ x) {
    __shared__ float t[32][33];
    const int tx = threadIdx.x & 31, ty = threadIdx.x >> 5;
    const int l0 = blockIdx.x << 5;
    const int c0 = blockIdx.y << 5;
    const int b  = blockIdx.z;
    const float* xb = x + ((size_t)b * CIN + c0) * L_ + l0;
#pragma unroll
    for (int i = 0; i < 4; ++i)
        t[ty + i * 8][tx] = xb[(size_t)(ty + i * 8) * L_ + tx];
    __syncthreads();
    float* ob = d_xT + ((size_t)b * L_ + l0) * CIN + c0;
#pragma unroll
    for (int i = 0; i < 4; ++i)
        ob[(size_t)(ty + i * 8) * CIN + tx] = t[tx][ty + i * 8];
}

// ---------------------------------------------------------------------------
// Kernel 1: bilinear metadata (validated)
// ---------------------------------------------------------------------------
__global__ void meta_kernel(const float* __restrict__ anc) {
    int g = blockIdx.x * blockDim.x + threadIdx.x;
    if (g >= B_ * K2_ * L_) return;
    int l = g % L_, k2 = (g / L_) % K2_, b = g / (L_ * K2_);

    const float* a = anc + (size_t)(b * L_ + l) * 5;
    float xc = a[0] * 0.125f, yc = a[1] * 0.125f;
    float dw = (a[2] * 0.125f) / 3.0f, dh = (a[3] * 0.125f) / 3.0f;
    float s, c;
    sincosf(a[4], &s, &c);
    float fx = (float)(k2 % 3) - 1.0f, fy = (float)(k2 / 3) - 1.0f;
    float xk = dw * fx, yk = dh * fy;
    float px = (c * xk - s * yk) + xc;
    float py = (s * xk + c * yk) + yc;

    float x0f = floorf(px), y0f = floorf(py);
    int x0 = (int)x0f, y0 = (int)y0f;
    float wx1 = px - x0f, wy1 = py - y0f;
    float wx0 = 1.0f - wx1, wy0 = 1.0f - wy1;
    int x1 = x0 + 1, y1 = y0 + 1;
    float vx0 = (x0 >= 0 && x0 < W_) ? 1.f : 0.f;
    float vx1 = (x1 >= 0 && x1 < W_) ? 1.f : 0.f;
    float vy0 = (y0 >= 0 && y0 < H_) ? 1.f : 0.f;
    float vy1 = (y1 >= 0 && y1 < H_) ? 1.f : 0.f;
    int xc0 = min(max(x0, 0), W_ - 1), xc1 = min(max(x1, 0), W_ - 1);
    int yc0 = min(max(y0, 0), H_ - 1), yc1 = min(max(y1, 0), H_ - 1);
    d_mi[g] = make_int4(yc0 * W_ + xc0, yc0 * W_ + xc1,
                        yc1 * W_ + xc0, yc1 * W_ + xc1);
    d_mw[g] = make_float4(wy0 * wx0 * vy0 * vx0, wy0 * wx1 * vy0 * vx1,
                          wy1 * wx0 * vy1 * vx0, wy1 * wx1 * vy1 * vx1);
}

// ---------------------------------------------------------------------------
// Kernel 2: bake B into mma fragment order, single fp16 matrix (validated).
// chunk16 c = 16*k2 + ci/16; chunk32 nc uses c = 2*nc + sub (same ordering).
// ---------------------------------------------------------------------------
__global__ void bf_kernel(const float* __restrict__ w) {
    int i = blockIdx.x * blockDim.x + threadIdx.x;
    if (i >= NCH16 * 2048) return;
    int chunk = i >> 11;
    int r2    = i & 2047;
    int tile  = r2 >> 6;
    int lane  = (r2 >> 1) & 31;
    int reg   = r2 & 1;

    int co = tile * 8 + (lane >> 2);
    int kb = 2 * (lane & 3) + 8 * reg;
    int ci = (chunk & 15) * 16 + kb;
    int k2 = chunk >> 4;

    float v0 = w[((size_t)co * CIN + ci) * K2_ + k2];
    float v1 = w[((size_t)co * CIN + ci + 1) * K2_ + k2];
    d_Bf[i] = pack16(v0, v1);
}

// ---------------------------------------------------------------------------
// Kernel 3: implicit GEMM, mma.sync fp16, 32-ci chunks.
//   CTA: M=64 px x N=256 couts, 256 threads (8 warps: 2M x 4N).
//   Gather: thread (q=tid&7 ci-quartet, pxh=tid>>3) handles pixels pxh and
//   pxh+32; per corner one LDG.128 where the 8 q-lanes of a pixel cover one
//   full 128B line (touched exactly once).
// ---------------------------------------------------------------------------
__global__ __launch_bounds__(256, 2)
void gemm_kernel(float* __restrict__ out) {
    __shared__ uint4 smem4[2 * BUF_BYTES / 16];   // 40 KB
    char* smem = (char*)smem4;
    const unsigned smem_b = (unsigned)__cvta_generic_to_shared(smem);

    const int tid  = threadIdx.x;
    const int lane = tid & 31;
    const int wid  = tid >> 5;
    const int b    = blockIdx.x >> 6;
    const int l0   = (blockIdx.x & 63) << 6;   // 64-pixel tiles
    const int q    = tid & 7;                  // ci quartet within 32-chunk
    const int pxh  = tid >> 3;                 // pixel (0..31); also handles +32

    // --- producer A STS base offset (pixel pxh, t=0). Variants:
    //     t=1 -> ^16 ; pixel pxh+32 -> +1024 (mt += 2)
    const int r  = pxh & 15, mt = pxh >> 4;
    const int rs = (r >> 1) & 3;
    const int pk = 2 * (q & 3);
    const int sa0 = (mt * 32 + ((((r & 7) << 2) | (pk & 3)) ^ rs)) * 16
                  + (2 * (pk >= 4) + (r >= 8)) * 4;
    const int suba = (q >> 2) * 2048;          // sub-chunk region

    // --- consumer fragment bases (immediate offsets used per tile) ---
    const int ca0 = (wid & 1) * 1024 + (lane ^ ((lane >> 3) & 3)) * 16;
    const int bo0 = (wid >> 1) * 2048 + lane * 8;

    float acc[2][8][4];
#pragma unroll
    for (int i = 0; i < 2; ++i)
#pragma unroll
        for (int t = 0; t < 8; ++t)
#pragma unroll
            for (int w0 = 0; w0 < 4; ++w0) acc[i][t][w0] = 0.0f;

    const float* xTb = d_xT + (size_t)b * L_ * CIN;
    int4 mia, mib; float4 mwa, mwb;
    {
        int mx = (b * K2_) * L_ + l0 + pxh;
        mia = d_mi[mx];      mwa = d_mw[mx];
        mib = d_mi[mx + 32]; mwb = d_mw[mx + 32];
    }

    // ---- prologue: chunk 0 -> buffer 0 ----
    {
#pragma unroll
        for (int i = 0; i < 4; ++i)
            cp16(smem_b + 4096 + (tid + i * 256) * 16,
                 d_Bf + (tid + i * 256) * 4);
        CP_COMMIT();

        const float* basep = xTb + 4 * q;
        float4 a0 = __ldg((const float4*)(basep + ((size_t)mia.x << 8)));
        float4 a1 = __ldg((const float4*)(basep + ((size_t)mia.y << 8)));
        float4 a2 = __ldg((const float4*)(basep + ((size_t)mia.z << 8)));
        float4 a3 = __ldg((const float4*)(basep + ((size_t)mia.w << 8)));
        float4 c0 = __ldg((const float4*)(basep + ((size_t)mib.x << 8)));
        float4 c1 = __ldg((const float4*)(basep + ((size_t)mib.y << 8)));
        float4 c2 = __ldg((const float4*)(basep + ((size_t)mib.z << 8)));
        float4 c3 = __ldg((const float4*)(basep + ((size_t)mib.w << 8)));
        char* An = smem + suba;
        *(unsigned*)(An + sa0) = pack16(
            mwa.x * a0.x + mwa.y * a1.x + mwa.z * a2.x + mwa.w * a3.x,
            mwa.x * a0.y + mwa.y * a1.y + mwa.z * a2.y + mwa.w * a3.y);
        *(unsigned*)(An + (sa0 ^ 16)) = pack16(
            mwa.x * a0.z + mwa.y * a1.z + mwa.z * a2.z + mwa.w * a3.z,
            mwa.x * a0.w + mwa.y * a1.w + mwa.z * a2.w + mwa.w * a3.w);
        *(unsigned*)(An + 1024 + sa0) = pack16(
            mwb.x * c0.x + mwb.y * c1.x + mwb.z * c2.x + mwb.w * c3.x,
            mwb.x * c0.y + mwb.y * c1.y + mwb.z * c2.y + mwb.w * c3.y);
        *(unsigned*)(An + 1024 + (sa0 ^ 16)) = pack16(
            mwb.x * c0.z + mwb.y * c1.z + mwb.z * c2.z + mwb.w * c3.z,
            mwb.x * c0.w + mwb.y * c1.w + mwb.z * c2.w + mwb.w * c3.w);
        CP_WAIT0();
    }
    __syncthreads();

    for (int ch = 0; ch < NCH; ++ch) {
        const int buf = ch & 1;
        const bool more = (ch + 1) < NCH;

        // ---- math on current buffer: 2 sub-chunks x 16 MMA ----
        {
            char* Ab = smem + buf * BUF_BYTES;
#pragma unroll
            for (int sub = 0; sub < 2; ++sub) {
                const char* Ar = Ab + sub * 2048;
                const char* Br = Ab + 4096 + sub * 8192;
                uint4 ah0 = *(const uint4*)(Ar + ca0);
                uint4 ah1 = *(const uint4*)(Ar + ca0 + 512);
                uint2 bb[8];
#pragma unroll
                for (int t = 0; t < 8; ++t)
                    bb[t] = *(const uint2*)(Br + bo0 + t * 256);
#pragma unroll
                for (int t = 0; t < 8; ++t) {
                    mma_fp16(acc[0][t], (const unsigned*)&ah0,
                             (const unsigned*)&bb[t]);
                    mma_fp16(acc[1][t], (const unsigned*)&ah1,
                             (const unsigned*)&bb[t]);
                }
            }
        }

        if (more) {
            const int nc = ch + 1;
            if ((nc & 7) == 0) {
                int mx = (b * K2_ + (nc >> 3)) * L_ + l0 + pxh;
                mia = d_mi[mx];      mwa = d_mw[mx];
                mib = d_mi[mx + 32]; mwb = d_mw[mx + 32];
            }
            const unsigned dstB = smem_b + (buf ^ 1) * BUF_BYTES + 4096;
            const unsigned* srcB = d_Bf + nc * 4096;
#pragma unroll
            for (int i = 0; i < 4; ++i)
                cp16(dstB + (tid + i * 256) * 16, srcB + (tid + i * 256) * 4);
            CP_COMMIT();

            const float* basep = xTb + (nc & 7) * 32 + 4 * q;
            float4 a0 = __ldg((const float4*)(basep + ((size_t)mia.x << 8)));
            float4 a1 = __ldg((const float4*)(basep + ((size_t)mia.y << 8)));
            float4 a2 = __ldg((const float4*)(basep + ((size_t)mia.z << 8)));
            float4 a3 = __ldg((const float4*)(basep + ((size_t)mia.w << 8)));
            float4 c0 = __ldg((const float4*)(basep + ((size_t)mib.x << 8)));
            float4 c1 = __ldg((const float4*)(basep + ((size_t)mib.y << 8)));
            float4 c2 = __ldg((const float4*)(basep + ((size_t)mib.z << 8)));
            float4 c3 = __ldg((const float4*)(basep + ((size_t)mib.w << 8)));
            char* An = smem + (buf ^ 1) * BUF_BYTES + suba;
            *(unsigned*)(An + sa0) = pack16(
                mwa.x * a0.x + mwa.y * a1.x + mwa.z * a2.x + mwa.w * a3.x,
                mwa.x * a0.y + mwa.y * a1.y + mwa.z * a2.y + mwa.w * a3.y);
            *(unsigned*)(An + (sa0 ^ 16)) = pack16(
                mwa.x * a0.z + mwa.y * a1.z + mwa.z * a2.z + mwa.w * a3.z,
                mwa.x * a0.w + mwa.y * a1.w + mwa.z * a2.w + mwa.w * a3.w);
            *(unsigned*)(An + 1024 + sa0) = pack16(
                mwb.x * c0.x + mwb.y * c1.x + mwb.z * c2.x + mwb.w * c3.x,
                mwb.x * c0.y + mwb.y * c1.y + mwb.z * c2.y + mwb.w * c3.y);
            *(unsigned*)(An + 1024 + (sa0 ^ 16)) = pack16(
                mwb.x * c0.z + mwb.y * c1.z + mwb.z * c2.z + mwb.w * c3.z,
                mwb.x * c0.w + mwb.y * c1.w + mwb.z * c2.w + mwb.w * c3.w);
        }
        CP_WAIT0();
        __syncthreads();
    }

    // ---- epilogue: relu + direct stores (unchanged, validated) ----
    const int ncol = wid >> 1;
#pragma unroll
    for (int i = 0; i < 2; ++i) {
        int pxg = l0 + ((wid & 1) * 2 + i) * 16 + (lane >> 2);
#pragma unroll
        for (int t = 0; t < 8; ++t) {
            int co = ncol * 64 + t * 8 + 2 * (lane & 3);
            float* o0 = out + ((size_t)(b * COUT + co)) * L_ + pxg;
            float* o1 = o0 + L_;
            o0[0] = fmaxf(acc[i][t][0], 0.0f);
            o1[0] = fmaxf(acc[i][t][1], 0.0f);
            o0[8] = fmaxf(acc[i][t][2], 0.0f);
            o1[8] = fmaxf(acc[i][t][3], 0.0f);
        }
    }
}

// ---------------------------------------------------------------------------
extern "C" void kernel_launch(void* const* d_in, const int* in_sizes, int n_in,
                              void* d_out, int out_size) {
    const float* x   = (const float*)d_in[0];  // [8,256,64,64]
    const float* anc = (const float*)d_in[1];  // [8,4096,5]
    const float* w   = (const float*)d_in[2];  // [256,256,3,3]
    float* out = (float*)d_out;                // [8,256,64,64]

    tr_kernel<<<dim3(128, 8, 8), 256>>>(x);
    meta_kernel<<<(B_ * K2_ * L_ + 255) / 256, 256>>>(anc);
    bf_kernel<<<(NCH16 * 2048 + 255) / 256, 256>>>(w);
    gemm_kernel<<<512, 256>>>(out);
}